// round 1
// baseline (speedup 1.0000x reference)
#include <cuda_runtime.h>
#include <math.h>
#include <stdint.h>

#define DIM 128
#define NL 50000
#define NP 100000
#define ELL 500000
#define EPP 400000
#define ELP 500000
#define EPL 500000

// ---------------- scratch (device globals; allocation-free rule) ----------------
__device__ __align__(16) float g_xL[NL * DIM];
__device__ __align__(16) float g_xP[NP * DIM];
__device__ __align__(16) float g_legoA[NL * DIM];
__device__ __align__(16) float g_pointA[NP * DIM];
__device__ __align__(16) float g_q[NL * DIM];
__device__ __align__(16) float g_k[NL * DIM];
__device__ __align__(16) float g_v[NL * DIM];
__device__ __align__(16) float g_hs[NP * DIM];
__device__ __align__(16) float g_A512[NP * 512];
__device__ __align__(16) float g_B512[NP * 512];
__device__ __align__(16) float g_W1c[128 * 512];
__device__ __align__(16) float g_esc[500000];
__device__ __align__(16) float g_nmax[NP];
__device__ __align__(16) float g_nsum[NP];
__device__ __align__(16) float g_ssrc[NP];
__device__ __align__(16) float g_sdst[NP];
__device__ __align__(16) float g_waD[DIM];

// ---------------- small device helpers ----------------
__device__ __forceinline__ unsigned long long pack_dup(float x) {
    unsigned long long r;
    asm("mov.b64 %0, {%1, %1};" : "=l"(r) : "f"(x));
    return r;
}
__device__ __forceinline__ void ffma2(unsigned long long& d, unsigned long long a, unsigned long long b) {
    asm("fma.rn.f32x2 %0, %1, %2, %0;" : "+l"(d) : "l"(a), "l"(b));
}
__device__ __forceinline__ float2 unpk(unsigned long long u) {
    float2 f;
    asm("mov.b64 {%0, %1}, %2;" : "=f"(f.x), "=f"(f.y) : "l"(u));
    return f;
}
__device__ __forceinline__ void atomicMaxF(float* a, float v) {
    if (v >= 0.f) atomicMax((int*)a, __float_as_int(v));
    else          atomicMin((unsigned int*)a, __float_as_uint(v));
}

// ---------------- generic tiled GEMM: C[M,N] = X[M,128] @ W[128,N] (+bias) ----------------
// CTA tile 64 rows x 128 cols, 256 threads, thread tile 4x8, f32x2 packed FMA.
__global__ __launch_bounds__(256) void gemm_tile(
    const float* __restrict__ X, const float* __restrict__ W,
    const float* __restrict__ bias, float* __restrict__ C,
    int M, int ldw, int ldc) {
    __shared__ __align__(16) float sX[64][36];
    __shared__ __align__(16) float sW[32][128];
    int t = threadIdx.x;
    int rowBase = blockIdx.x * 64;
    int colBase = blockIdx.y * 128;
    int rg = t >> 4, cg = t & 15;
    int r0 = rg * 4, c0 = cg * 8;
    unsigned long long acc[4][4];
#pragma unroll
    for (int r = 0; r < 4; r++)
#pragma unroll
        for (int p = 0; p < 4; p++) acc[r][p] = 0ull;
    int rA = t >> 3, kA = (t & 7) * 4;
    for (int kb = 0; kb < 128; kb += 32) {
#pragma unroll
        for (int i = 0; i < 2; i++) {
            int r = rA + i * 32;
            int row = rowBase + r; if (row >= M) row = M - 1;
            *(float4*)&sX[r][kA] = *(const float4*)&X[(size_t)row * 128 + kb + kA];
        }
#pragma unroll
        for (int i = 0; i < 4; i++) {
            int lin = t + i * 256;
            int k = lin >> 5, c4 = (lin & 31) * 4;
            *(float4*)&sW[k][c4] = *(const float4*)&W[(size_t)(kb + k) * ldw + colBase + c4];
        }
        __syncthreads();
#pragma unroll
        for (int k = 0; k < 32; k++) {
            ulonglong2 wa = *(const ulonglong2*)&sW[k][c0];
            ulonglong2 wb = *(const ulonglong2*)&sW[k][c0 + 4];
#pragma unroll
            for (int r = 0; r < 4; r++) {
                unsigned long long hp = pack_dup(sX[r0 + r][k]);
                ffma2(acc[r][0], hp, wa.x);
                ffma2(acc[r][1], hp, wa.y);
                ffma2(acc[r][2], hp, wb.x);
                ffma2(acc[r][3], hp, wb.y);
            }
        }
        __syncthreads();
    }
#pragma unroll
    for (int r = 0; r < 4; r++) {
        int row = rowBase + r0 + r;
        if (row >= M) continue;
        float o[8];
#pragma unroll
        for (int p = 0; p < 4; p++) { float2 f = unpk(acc[r][p]); o[2*p] = f.x; o[2*p+1] = f.y; }
        if (bias) {
#pragma unroll
            for (int j = 0; j < 8; j++) o[j] += bias[colBase + c0 + j];
        }
        *(float4*)&C[(size_t)row * ldc + colBase + c0]     = make_float4(o[0], o[1], o[2], o[3]);
        *(float4*)&C[(size_t)row * ldc + colBase + c0 + 4] = make_float4(o[4], o[5], o[6], o[7]);
    }
}

// ---------------- EdgeConv second layer: per-edge gathered GEMM [E,512]@[512,128] + seg-max ----------------
__global__ __launch_bounds__(256) void edge_mlp2(
    const float* __restrict__ Ad, const float* __restrict__ Bs,
    const int* __restrict__ src, const int* __restrict__ dst,
    const float* __restrict__ W2, const float* __restrict__ b2,
    float* __restrict__ out, int E) {
    __shared__ __align__(16) float sH[64][36];
    __shared__ __align__(16) float sW[32][128];
    __shared__ int sSrc[64], sDst[64];
    int t = threadIdx.x;
    int eBase = blockIdx.x * 64;
    if (t < 64) {
        int e = eBase + t;
        sSrc[t] = (e < E) ? src[e] : 0;
        sDst[t] = (e < E) ? dst[e] : 0;
    }
    __syncthreads();
    int rg = t >> 4, cg = t & 15;
    int r0 = rg * 4, c0 = cg * 8;
    unsigned long long acc[4][4];
#pragma unroll
    for (int r = 0; r < 4; r++)
#pragma unroll
        for (int p = 0; p < 4; p++) acc[r][p] = 0ull;
    int rA = t >> 3, kA = (t & 7) * 4;
    for (int kb = 0; kb < 512; kb += 32) {
#pragma unroll
        for (int i = 0; i < 2; i++) {
            int r = rA + i * 32;
            float4 a = *(const float4*)&Ad[(size_t)sDst[r] * 512 + kb + kA];
            float4 b = *(const float4*)&Bs[(size_t)sSrc[r] * 512 + kb + kA];
            float4 h;
            h.x = fmaxf(a.x + b.x, 0.f);
            h.y = fmaxf(a.y + b.y, 0.f);
            h.z = fmaxf(a.z + b.z, 0.f);
            h.w = fmaxf(a.w + b.w, 0.f);
            *(float4*)&sH[r][kA] = h;
        }
#pragma unroll
        for (int i = 0; i < 4; i++) {
            int lin = t + i * 256;
            int k = lin >> 5, c4 = (lin & 31) * 4;
            *(float4*)&sW[k][c4] = *(const float4*)&W2[(size_t)(kb + k) * 128 + c4];
        }
        __syncthreads();
#pragma unroll
        for (int k = 0; k < 32; k++) {
            ulonglong2 wa = *(const ulonglong2*)&sW[k][c0];
            ulonglong2 wb = *(const ulonglong2*)&sW[k][c0 + 4];
#pragma unroll
            for (int r = 0; r < 4; r++) {
                unsigned long long hp = pack_dup(sH[r0 + r][k]);
                ffma2(acc[r][0], hp, wa.x);
                ffma2(acc[r][1], hp, wa.y);
                ffma2(acc[r][2], hp, wb.x);
                ffma2(acc[r][3], hp, wb.y);
            }
        }
        __syncthreads();
    }
#pragma unroll
    for (int r = 0; r < 4; r++) {
        int eid = eBase + r0 + r;
        if (eid >= E) continue;
        int d = sDst[r0 + r];
        float* orow = &out[(size_t)d * 128];
#pragma unroll
        for (int p = 0; p < 4; p++) {
            float2 f = unpk(acc[r][p]);
            int c = c0 + 2 * p;
            atomicMaxF(orow + c,     f.x + b2[c]);
            atomicMaxF(orow + c + 1, f.y + b2[c + 1]);
        }
    }
}

// ---------------- edge / elementwise kernels ----------------
__global__ void fillk(float* __restrict__ p, int n, float v) {
    int i = blockIdx.x * blockDim.x + threadIdx.x;
    if (i < n) p[i] = v;
}
__global__ void w1ck(const float* __restrict__ W1, float* __restrict__ W1c) {
    int i = blockIdx.x * blockDim.x + threadIdx.x;
    if (i < 128 * 512) W1c[i] = W1[i] - W1[i + 128 * 512];
}
__global__ void finalize_max(float* __restrict__ p, int n) {
    int i = blockIdx.x * blockDim.x + threadIdx.x;
    if (i < n) { float v = p[i]; if (v < -3.0e38f) p[i] = 0.f; }
}
__global__ void bias_add(float* __restrict__ out, const float* __restrict__ b, int n) {
    int i = blockIdx.x * blockDim.x + threadIdx.x;
    if (i < n) out[i] += b[i & 127];
}
// out[i] = dot(X[i, 0:128], v)   (warp per row)
__global__ void rowdot(const float* __restrict__ X, const float* __restrict__ v,
                       float* __restrict__ out, int M) {
    int w = (blockIdx.x * blockDim.x + threadIdx.x) >> 5;
    int lane = threadIdx.x & 31;
    if (w >= M) return;
    float4 x = *(const float4*)&X[(size_t)w * 128 + lane * 4];
    float4 vv = *(const float4*)&v[lane * 4];
    float p = x.x * vv.x + x.y * vv.y + x.z * vv.z + x.w * vv.w;
#pragma unroll
    for (int o = 16; o; o >>= 1) p += __shfl_xor_sync(0xffffffffu, p, o);
    if (lane == 0) out[w] = p;
}
// Transformer score: s = dot(q[dst], k[src]) / sqrt(128), seg-max (warp per edge)
__global__ void trans_score_k(const float* __restrict__ q, const float* __restrict__ k,
                              const int* __restrict__ src, const int* __restrict__ dst,
                              float* __restrict__ score, float* __restrict__ nmax, int E) {
    int w = (blockIdx.x * blockDim.x + threadIdx.x) >> 5;
    int lane = threadIdx.x & 31;
    if (w >= E) return;
    int s = src[w], d = dst[w];
    float4 a = *(const float4*)&q[(size_t)d * 128 + lane * 4];
    float4 b = *(const float4*)&k[(size_t)s * 128 + lane * 4];
    float p = a.x * b.x + a.y * b.y + a.z * b.z + a.w * b.w;
#pragma unroll
    for (int o = 16; o; o >>= 1) p += __shfl_xor_sync(0xffffffffu, p, o);
    if (lane == 0) {
        p *= 0.08838834764831845f;  // 1/sqrt(128)
        score[w] = p;
        atomicMaxF(&nmax[d], p);
    }
}
// GAT score: leaky_relu(ssrc[src] + sdst[dst], 0.2), seg-max (thread per edge)
__global__ void gat_score_k(const float* __restrict__ ssrc, const float* __restrict__ sdst,
                            const int* __restrict__ src, const int* __restrict__ dst,
                            float* __restrict__ score, float* __restrict__ nmax, int E) {
    int e = blockIdx.x * blockDim.x + threadIdx.x;
    if (e >= E) return;
    float s = ssrc[src[e]] + sdst[dst[e]];
    s = (s > 0.f) ? s : 0.2f * s;
    score[e] = s;
    atomicMaxF(&nmax[dst[e]], s);
}
__global__ void expnorm_k(float* __restrict__ score, const int* __restrict__ dst,
                          const float* __restrict__ nmax, float* __restrict__ nsum, int E) {
    int e = blockIdx.x * blockDim.x + threadIdx.x;
    if (e >= E) return;
    int d = dst[e];
    float v = __expf(score[e] - nmax[d]);
    score[e] = v;
    atomicAdd(&nsum[d], v);
}
// out[dst] += (score[e]/sum[dst]) * V[src]  (warp per edge)
__global__ void scatter_k(const float* __restrict__ score, const float* __restrict__ nsum,
                          const float* __restrict__ V,
                          const int* __restrict__ src, const int* __restrict__ dst,
                          float* __restrict__ out, int E) {
    int w = (blockIdx.x * blockDim.x + threadIdx.x) >> 5;
    int lane = threadIdx.x & 31;
    if (w >= E) return;
    int s = src[w], d = dst[w];
    float a = score[w] / (nsum[d] + 1e-16f);
    float4 v = *(const float4*)&V[(size_t)s * 128 + lane * 4];
    float* o = &out[(size_t)d * 128 + lane * 4];
    atomicAdd(o + 0, a * v.x);
    atomicAdd(o + 1, a * v.y);
    atomicAdd(o + 2, a * v.z);
    atomicAdd(o + 3, a * v.w);
}

// ---------------- host orchestration ----------------
static inline void run_gemm(const float* X, const float* W, const float* bias,
                            float* C, int M, int N, int ldw) {
    dim3 grid((M + 63) / 64, N / 128);
    gemm_tile<<<grid, 256>>>(X, W, bias, C, M, ldw, N);
}

struct Scratch {
    float *xL, *xP, *legoA, *pointA, *q, *k, *v, *hs, *A512, *B512, *W1c;
    float *esc, *nmax, *nsum, *ssrc, *sdst, *waD;
};

static void trans_conv(const Scratch& S, const float* x, int Nn,
                       const int* src, const int* dst, int E,
                       const float* Wq, const float* bq, const float* Wk, const float* bk,
                       const float* Wv, const float* bv, const float* Ws, const float* bs,
                       float* out) {
    run_gemm(x, Wq, bq, S.q, Nn, 128, 128);
    run_gemm(x, Wk, bk, S.k, Nn, 128, 128);
    run_gemm(x, Wv, bv, S.v, Nn, 128, 128);
    run_gemm(x, Ws, bs, out, Nn, 128, 128);   // root/skip contribution
    fillk<<<(Nn + 255) / 256, 256>>>(S.nmax, Nn, -INFINITY);
    fillk<<<(Nn + 255) / 256, 256>>>(S.nsum, Nn, 0.f);
    trans_score_k<<<(E + 7) / 8, 256>>>(S.q, S.k, src, dst, S.esc, S.nmax, E);
    expnorm_k<<<(E + 255) / 256, 256>>>(S.esc, dst, S.nmax, S.nsum, E);
    scatter_k<<<(E + 7) / 8, 256>>>(S.esc, S.nsum, S.v, src, dst, out, E);
}

static void gat_conv(const Scratch& S, const float* xs, int Ns, const float* xd, int Nd,
                     const int* src, const int* dst, int E,
                     const float* W, const float* As, const float* Ad, const float* b,
                     float* out /* accumulated */) {
    run_gemm(xs, W, nullptr, S.hs, Ns, 128, 128);
    rowdot<<<(128 + 7) / 8, 256>>>(W, Ad, S.waD, 128);        // waD = W @ a_dst
    rowdot<<<(Ns + 7) / 8, 256>>>(S.hs, As, S.ssrc, Ns);      // ssrc = hs @ a_src
    rowdot<<<(Nd + 7) / 8, 256>>>(xd, S.waD, S.sdst, Nd);     // sdst = xd @ waD
    fillk<<<(Nd + 255) / 256, 256>>>(S.nmax, Nd, -INFINITY);
    fillk<<<(Nd + 255) / 256, 256>>>(S.nsum, Nd, 0.f);
    gat_score_k<<<(E + 255) / 256, 256>>>(S.ssrc, S.sdst, src, dst, S.esc, S.nmax, E);
    expnorm_k<<<(E + 255) / 256, 256>>>(S.esc, dst, S.nmax, S.nsum, E);
    scatter_k<<<(E + 7) / 8, 256>>>(S.esc, S.nsum, S.hs, src, dst, out, E);
    bias_add<<<(Nd * 128 + 255) / 256, 256>>>(out, b, Nd * 128);
}

static void edge_conv(const Scratch& S, const float* x, int Nn,
                      const int* src, const int* dst, int E,
                      const float* W1, const float* b1, const float* W2, const float* b2,
                      float* out) {
    w1ck<<<(128 * 512) / 256, 256>>>(W1, S.W1c);              // W1top - W1bot
    run_gemm(x, S.W1c, b1, S.A512, Nn, 512, 512);             // A = x@(W1top-W1bot)+b1  (dst side)
    run_gemm(x, W1 + 128 * 512, nullptr, S.B512, Nn, 512, 512); // B = x@W1bot          (src side)
    fillk<<<(Nn * 128 + 255) / 256, 256>>>(out, Nn * 128, -INFINITY);
    edge_mlp2<<<(E + 63) / 64, 256>>>(S.A512, S.B512, src, dst, W2, b2, out, E);
    finalize_max<<<(Nn * 128 + 255) / 256, 256>>>(out, Nn * 128);
}

#define GETSYM(field, symbol) do { void* _p; cudaGetSymbolAddress(&_p, symbol); S.field = (float*)_p; } while (0)

extern "C" void kernel_launch(void* const* d_in, const int* in_sizes, int n_in,
                              void* d_out, int out_size) {
    const float* in_xL  = (const float*)d_in[0];
    const float* in_xP  = (const float*)d_in[1];
    const float* tWq = (const float*)d_in[2];
    const float* tbq = (const float*)d_in[3];
    const float* tWk = (const float*)d_in[4];
    const float* tbk = (const float*)d_in[5];
    const float* tWv = (const float*)d_in[6];
    const float* tbv = (const float*)d_in[7];
    const float* tWs = (const float*)d_in[8];
    const float* tbs = (const float*)d_in[9];
    const float* eW1 = (const float*)d_in[10];
    const float* eb1 = (const float*)d_in[11];
    const float* eW2 = (const float*)d_in[12];
    const float* eb2 = (const float*)d_in[13];
    const float* gW  = (const float*)d_in[14];
    const float* gAs = (const float*)d_in[15];
    const float* gAd = (const float*)d_in[16];
    const float* gb  = (const float*)d_in[17];
    const int* ll_src = (const int*)d_in[18];
    const int* ll_dst = (const int*)d_in[19];
    const int* pp_src = (const int*)d_in[20];
    const int* pp_dst = (const int*)d_in[21];
    const int* lp_src = (const int*)d_in[22];
    const int* lp_dst = (const int*)d_in[23];
    const int* pl_src = (const int*)d_in[24];
    const int* pl_dst = (const int*)d_in[25];

    Scratch S;
    GETSYM(xL, g_xL);       GETSYM(xP, g_xP);
    GETSYM(legoA, g_legoA); GETSYM(pointA, g_pointA);
    GETSYM(q, g_q); GETSYM(k, g_k); GETSYM(v, g_v); GETSYM(hs, g_hs);
    GETSYM(A512, g_A512); GETSYM(B512, g_B512); GETSYM(W1c, g_W1c);
    GETSYM(esc, g_esc); GETSYM(nmax, g_nmax); GETSYM(nsum, g_nsum);
    GETSYM(ssrc, g_ssrc); GETSYM(sdst, g_sdst); GETSYM(waD, g_waD);

    cudaMemcpyAsync(S.xL, in_xL, (size_t)NL * DIM * sizeof(float), cudaMemcpyDeviceToDevice);
    cudaMemcpyAsync(S.xP, in_xP, (size_t)NP * DIM * sizeof(float), cudaMemcpyDeviceToDevice);

    for (int layer = 0; layer < 2; layer++) {
        int iA = 2 * layer, iB = 2 * layer + 1;
        int ilp = 2 * layer, ipl = 2 * layer + 1;

        // ---- conv A (heterogeneous, sum aggregation per dst type) ----
        // lego_a = trans(xL, ll) + gat(xP -> xL, pl)
        trans_conv(S, S.xL, NL, ll_src, ll_dst, ELL,
                   tWq + iA * 16384, tbq + iA * 128, tWk + iA * 16384, tbk + iA * 128,
                   tWv + iA * 16384, tbv + iA * 128, tWs + iA * 16384, tbs + iA * 128,
                   S.legoA);
        gat_conv(S, S.xP, NP, S.xL, NL, pl_src, pl_dst, EPL,
                 gW + ipl * 16384, gAs + ipl * 128, gAd + ipl * 128, gb + ipl * 128,
                 S.legoA);
        // point_a = edge(xP, pp) + gat(xL -> xP, lp)
        edge_conv(S, S.xP, NP, pp_src, pp_dst, EPP,
                  eW1 + iA * 131072, eb1 + iA * 512, eW2 + iA * 65536, eb2 + iA * 128,
                  S.pointA);
        gat_conv(S, S.xL, NL, S.xP, NP, lp_src, lp_dst, ELP,
                 gW + ilp * 16384, gAs + ilp * 128, gAd + ilp * 128, gb + ilp * 128,
                 S.pointA);

        // ---- conv B (intra-type only) ----
        trans_conv(S, S.legoA, NL, ll_src, ll_dst, ELL,
                   tWq + iB * 16384, tbq + iB * 128, tWk + iB * 16384, tbk + iB * 128,
                   tWv + iB * 16384, tbv + iB * 128, tWs + iB * 16384, tbs + iB * 128,
                   S.xL);
        edge_conv(S, S.pointA, NP, pp_src, pp_dst, EPP,
                  eW1 + iB * 131072, eb1 + iB * 512, eW2 + iB * 65536, eb2 + iB * 128,
                  S.xP);
    }

    float* out = (float*)d_out;
    cudaMemcpyAsync(out, S.xL, (size_t)NL * DIM * sizeof(float), cudaMemcpyDeviceToDevice);
    cudaMemcpyAsync(out + (size_t)NL * DIM, S.xP, (size_t)NP * DIM * sizeof(float), cudaMemcpyDeviceToDevice);
}

// round 3
// speedup vs baseline: 1.9019x; 1.9019x over previous
#include <cuda_runtime.h>
#include <math.h>
#include <stdint.h>

#define DIM 128
#define NL 50000
#define NP 100000
#define ELL 500000
#define EPP 400000
#define ELP 500000
#define EPL 500000

// ---------------- scratch (device globals; allocation-free rule) ----------------
__device__ __align__(16) float g_xL[NL * DIM];
__device__ __align__(16) float g_xP[NP * DIM];
__device__ __align__(16) float g_legoA[NL * DIM];
__device__ __align__(16) float g_pointA[NP * DIM];
__device__ __align__(16) float g_q[NL * DIM];
__device__ __align__(16) float g_k[NL * DIM];
__device__ __align__(16) float g_v[NL * DIM];
__device__ __align__(16) float g_hs[NP * DIM];
__device__ __align__(16) float g_A512[NP * 512];
__device__ __align__(16) float g_B512[NP * 512];
__device__ __align__(16) float g_Wt1c[512 * 128];
__device__ __align__(16) float g_Wt1b[512 * 128];
__device__ __align__(16) float g_W2t[128 * 512];
__device__ __align__(16) float g_esc[500000];
__device__ __align__(16) float g_nmax[NP];
__device__ __align__(16) float g_nsum[NP];
__device__ __align__(16) float g_ssrc[NP];
__device__ __align__(16) float g_sdst[NP];
__device__ __align__(16) float g_waD[DIM];

// ---------------- small device helpers ----------------
__device__ __forceinline__ unsigned long long pack_dup(float x) {
    unsigned long long r;
    asm("mov.b64 %0, {%1, %1};" : "=l"(r) : "f"(x));
    return r;
}
__device__ __forceinline__ void ffma2(unsigned long long& d, unsigned long long a, unsigned long long b) {
    asm("fma.rn.f32x2 %0, %1, %2, %0;" : "+l"(d) : "l"(a), "l"(b));
}
__device__ __forceinline__ float2 unpk(unsigned long long u) {
    float2 f;
    asm("mov.b64 {%0, %1}, %2;" : "=f"(f.x), "=f"(f.y) : "l"(u));
    return f;
}
__device__ __forceinline__ void atomicMaxF(float* a, float v) {
    if (v >= 0.f) atomicMax((int*)a, __float_as_int(v));
    else          atomicMin((unsigned int*)a, __float_as_uint(v));
}
__device__ __forceinline__ uint32_t to_tf32(float x) {
    uint32_t r;
    asm("cvt.rna.tf32.f32 %0, %1;" : "=r"(r) : "f"(x));
    return r;
}
__device__ __forceinline__ void ldsm4(uint32_t& r0, uint32_t& r1, uint32_t& r2, uint32_t& r3, uint32_t addr) {
    asm volatile("ldmatrix.sync.aligned.m8n8.x4.shared.b16 {%0,%1,%2,%3}, [%4];"
                 : "=r"(r0), "=r"(r1), "=r"(r2), "=r"(r3) : "r"(addr));
}
__device__ __forceinline__ void mma_tf32(float* c, uint32_t a0, uint32_t a1, uint32_t a2, uint32_t a3,
                                         uint32_t b0, uint32_t b1) {
    asm volatile("mma.sync.aligned.m16n8k8.row.col.f32.tf32.tf32.f32 "
                 "{%0,%1,%2,%3},{%4,%5,%6,%7},{%8,%9},{%0,%1,%2,%3};"
                 : "+f"(c[0]), "+f"(c[1]), "+f"(c[2]), "+f"(c[3])
                 : "r"(a0), "r"(a1), "r"(a2), "r"(a3), "r"(b0), "r"(b1));
}

// ---------------- fp32 FFMA GEMM (kept for the exact N=128 lego-path GEMMs) ----------------
__global__ __launch_bounds__(256) void gemm_tile(
    const float* __restrict__ X, const float* __restrict__ W,
    const float* __restrict__ bias, float* __restrict__ C,
    int M, int ldw, int ldc) {
    __shared__ __align__(16) float sX[64][36];
    __shared__ __align__(16) float sW[32][128];
    int t = threadIdx.x;
    int rowBase = blockIdx.x * 64;
    int colBase = blockIdx.y * 128;
    int rg = t >> 4, cg = t & 15;
    int r0 = rg * 4, c0 = cg * 8;
    unsigned long long acc[4][4];
#pragma unroll
    for (int r = 0; r < 4; r++)
#pragma unroll
        for (int p = 0; p < 4; p++) acc[r][p] = 0ull;
    int rA = t >> 3, kA = (t & 7) * 4;
    for (int kb = 0; kb < 128; kb += 32) {
#pragma unroll
        for (int i = 0; i < 2; i++) {
            int r = rA + i * 32;
            int row = rowBase + r; if (row >= M) row = M - 1;
            *(float4*)&sX[r][kA] = *(const float4*)&X[(size_t)row * 128 + kb + kA];
        }
#pragma unroll
        for (int i = 0; i < 4; i++) {
            int lin = t + i * 256;
            int k = lin >> 5, c4 = (lin & 31) * 4;
            *(float4*)&sW[k][c4] = *(const float4*)&W[(size_t)(kb + k) * ldw + colBase + c4];
        }
        __syncthreads();
#pragma unroll
        for (int k = 0; k < 32; k++) {
            ulonglong2 wa = *(const ulonglong2*)&sW[k][c0];
            ulonglong2 wb = *(const ulonglong2*)&sW[k][c0 + 4];
#pragma unroll
            for (int r = 0; r < 4; r++) {
                unsigned long long hp = pack_dup(sX[r0 + r][k]);
                ffma2(acc[r][0], hp, wa.x);
                ffma2(acc[r][1], hp, wa.y);
                ffma2(acc[r][2], hp, wb.x);
                ffma2(acc[r][3], hp, wb.y);
            }
        }
        __syncthreads();
    }
#pragma unroll
    for (int r = 0; r < 4; r++) {
        int row = rowBase + r0 + r;
        if (row >= M) continue;
        float o[8];
#pragma unroll
        for (int p = 0; p < 4; p++) { float2 f = unpk(acc[r][p]); o[2*p] = f.x; o[2*p+1] = f.y; }
        if (bias) {
#pragma unroll
            for (int j = 0; j < 8; j++) o[j] += bias[colBase + c0 + j];
        }
        *(float4*)&C[(size_t)row * ldc + colBase + c0]     = make_float4(o[0], o[1], o[2], o[3]);
        *(float4*)&C[(size_t)row * ldc + colBase + c0 + 4] = make_float4(o[4], o[5], o[6], o[7]);
    }
}

// ---------------- tf32 tensor-core node GEMM: C[M,N] = X[M,128] @ W (Wt given as [N][128]) ----------------
// BM=128, BN=128, BK=32, 256 threads = 8 warps (2m x 4n), warp tile 64x32, mma m16n8k8.
__global__ __launch_bounds__(256, 2) void gemm_tf32(
    const float* __restrict__ X, const float* __restrict__ Wt,
    const float* __restrict__ bias, float* __restrict__ C, int M, int N) {
    __shared__ __align__(16) float sA[128 * 36];
    __shared__ __align__(16) float sB[128 * 36];
    int t = threadIdx.x;
    int rowBase = blockIdx.x * 128;
    int colBase = blockIdx.y * 128;
    uint32_t saBase = (uint32_t)__cvta_generic_to_shared(sA);
    uint32_t sbBase = (uint32_t)__cvta_generic_to_shared(sB);
    int warp = t >> 5, lane = t & 31;
    int wm = warp >> 2, wn = warp & 3;
    int mBase = wm * 64, nBase = wn * 32;
    int lr = lane & 15, lh = lane >> 4;
    float acc[4][4][4];
#pragma unroll
    for (int a = 0; a < 4; a++)
#pragma unroll
        for (int b = 0; b < 4; b++)
#pragma unroll
            for (int c = 0; c < 4; c++) acc[a][b][c] = 0.f;
    for (int k0 = 0; k0 < 128; k0 += 32) {
        __syncthreads();
#pragma unroll
        for (int i = 0; i < 4; i++) {
            int lin = t + i * 256;
            int r = lin >> 3, f4 = (lin & 7) * 4;
            int row = rowBase + r; if (row >= M) row = M - 1;
            float4 v = *(const float4*)&X[(size_t)row * 128 + k0 + f4];
            uint4 u = make_uint4(to_tf32(v.x), to_tf32(v.y), to_tf32(v.z), to_tf32(v.w));
            *(uint4*)&sA[r * 36 + f4] = u;
            float4 w = *(const float4*)&Wt[(size_t)(colBase + r) * 128 + k0 + f4];
            uint4 uw = make_uint4(to_tf32(w.x), to_tf32(w.y), to_tf32(w.z), to_tf32(w.w));
            *(uint4*)&sB[r * 36 + f4] = uw;
        }
        __syncthreads();
#pragma unroll
        for (int ks = 0; ks < 4; ks++) {
            uint32_t a[4][4], b[2][4];
#pragma unroll
            for (int mt = 0; mt < 4; mt++) {
                uint32_t addr = saBase + ((mBase + mt * 16 + lr) * 36 + ks * 8 + lh * 4) * 4;
                ldsm4(a[mt][0], a[mt][1], a[mt][2], a[mt][3], addr);
            }
#pragma unroll
            for (int p = 0; p < 2; p++) {
                uint32_t addr = sbBase + ((nBase + p * 16 + lr) * 36 + ks * 8 + lh * 4) * 4;
                ldsm4(b[p][0], b[p][1], b[p][2], b[p][3], addr);
            }
#pragma unroll
            for (int mt = 0; mt < 4; mt++)
#pragma unroll
                for (int nt = 0; nt < 4; nt++) {
                    int p = nt >> 1, wsel = nt & 1;
                    mma_tf32(acc[mt][nt], a[mt][0], a[mt][1], a[mt][2], a[mt][3],
                             b[p][wsel], b[p][2 + wsel]);
                }
        }
    }
    int g = lane >> 2, tq = lane & 3;
#pragma unroll
    for (int mt = 0; mt < 4; mt++)
#pragma unroll
        for (int nt = 0; nt < 4; nt++) {
            int col = colBase + nBase + nt * 8 + tq * 2;
            float b0 = bias ? bias[col] : 0.f;
            float b1 = bias ? bias[col + 1] : 0.f;
            int row = rowBase + mBase + mt * 16 + g;
            if (row < M)
                *(float2*)&C[(size_t)row * N + col] = make_float2(acc[mt][nt][0] + b0, acc[mt][nt][1] + b1);
            row += 8;
            if (row < M)
                *(float2*)&C[(size_t)row * N + col] = make_float2(acc[mt][nt][2] + b0, acc[mt][nt][3] + b1);
        }
}

// ---------------- tf32 EdgeConv 2nd layer: per-edge relu(A[dst]+B[src]) @ W2 + seg-max ----------------
// BM=128 edges, N=128 (full), K=512 in 16 chunks of 32.
__global__ __launch_bounds__(256, 2) void edge_mlp2_tf32(
    const float* __restrict__ Ad, const float* __restrict__ Bs,
    const int* __restrict__ src, const int* __restrict__ dst,
    const float* __restrict__ W2t, const float* __restrict__ b2,
    float* __restrict__ out, int E) {
    __shared__ __align__(16) float sA[128 * 36];
    __shared__ __align__(16) float sB[128 * 36];
    __shared__ int sSrc[128], sDst[128];
    int t = threadIdx.x;
    int eBase = blockIdx.x * 128;
    if (t < 128) {
        int e = eBase + t; if (e >= E) e = E - 1;
        sSrc[t] = src[e]; sDst[t] = dst[e];
    }
    uint32_t saBase = (uint32_t)__cvta_generic_to_shared(sA);
    uint32_t sbBase = (uint32_t)__cvta_generic_to_shared(sB);
    int warp = t >> 5, lane = t & 31;
    int wm = warp >> 2, wn = warp & 3;
    int mBase = wm * 64, nBase = wn * 32;
    int lr = lane & 15, lh = lane >> 4;
    float acc[4][4][4];
#pragma unroll
    for (int a = 0; a < 4; a++)
#pragma unroll
        for (int b = 0; b < 4; b++)
#pragma unroll
            for (int c = 0; c < 4; c++) acc[a][b][c] = 0.f;
    for (int k0 = 0; k0 < 512; k0 += 32) {
        __syncthreads();
#pragma unroll
        for (int i = 0; i < 4; i++) {
            int lin = t + i * 256;
            int r = lin >> 3, f4 = (lin & 7) * 4;
            float4 a = *(const float4*)&Ad[(size_t)sDst[r] * 512 + k0 + f4];
            float4 b = *(const float4*)&Bs[(size_t)sSrc[r] * 512 + k0 + f4];
            uint4 u = make_uint4(to_tf32(fmaxf(a.x + b.x, 0.f)), to_tf32(fmaxf(a.y + b.y, 0.f)),
                                 to_tf32(fmaxf(a.z + b.z, 0.f)), to_tf32(fmaxf(a.w + b.w, 0.f)));
            *(uint4*)&sA[r * 36 + f4] = u;
            float4 w = *(const float4*)&W2t[(size_t)r * 512 + k0 + f4];
            uint4 uw = make_uint4(to_tf32(w.x), to_tf32(w.y), to_tf32(w.z), to_tf32(w.w));
            *(uint4*)&sB[r * 36 + f4] = uw;
        }
        __syncthreads();
#pragma unroll
        for (int ks = 0; ks < 4; ks++) {
            uint32_t a[4][4], b[2][4];
#pragma unroll
            for (int mt = 0; mt < 4; mt++) {
                uint32_t addr = saBase + ((mBase + mt * 16 + lr) * 36 + ks * 8 + lh * 4) * 4;
                ldsm4(a[mt][0], a[mt][1], a[mt][2], a[mt][3], addr);
            }
#pragma unroll
            for (int p = 0; p < 2; p++) {
                uint32_t addr = sbBase + ((nBase + p * 16 + lr) * 36 + ks * 8 + lh * 4) * 4;
                ldsm4(b[p][0], b[p][1], b[p][2], b[p][3], addr);
            }
#pragma unroll
            for (int mt = 0; mt < 4; mt++)
#pragma unroll
                for (int nt = 0; nt < 4; nt++) {
                    int p = nt >> 1, wsel = nt & 1;
                    mma_tf32(acc[mt][nt], a[mt][0], a[mt][1], a[mt][2], a[mt][3],
                             b[p][wsel], b[p][2 + wsel]);
                }
        }
    }
    int g = lane >> 2, tq = lane & 3;
#pragma unroll
    for (int mt = 0; mt < 4; mt++)
#pragma unroll
        for (int nt = 0; nt < 4; nt++) {
            int col = nBase + nt * 8 + tq * 2;
            float b0 = b2[col], b1 = b2[col + 1];
            int r = mBase + mt * 16 + g;
            if (eBase + r < E) {
                float* o = &out[(size_t)sDst[r] * 128 + col];
                atomicMaxF(o,     acc[mt][nt][0] + b0);
                atomicMaxF(o + 1, acc[mt][nt][1] + b1);
            }
            r += 8;
            if (eBase + r < E) {
                float* o = &out[(size_t)sDst[r] * 128 + col];
                atomicMaxF(o,     acc[mt][nt][2] + b0);
                atomicMaxF(o + 1, acc[mt][nt][3] + b1);
            }
        }
}

// ---------------- weight transposes for tf32 path ----------------
// W1 [256][512]: WtC[n][k] = W1[k][n] - W1[k+128][n]; WtB[n][k] = W1[k+128][n]
__global__ void tr_w1(const float* __restrict__ W1, float* __restrict__ WtC, float* __restrict__ WtB) {
    __shared__ float tc[32][33], tb[32][33];
    int k0 = blockIdx.x * 32, n0 = blockIdx.y * 32;
    int tx = threadIdx.x, ty = threadIdx.y;
#pragma unroll
    for (int i = 0; i < 32; i += 8) {
        int k = k0 + ty + i, n = n0 + tx;
        float top = W1[k * 512 + n], bot = W1[(k + 128) * 512 + n];
        tc[ty + i][tx] = top - bot;
        tb[ty + i][tx] = bot;
    }
    __syncthreads();
#pragma unroll
    for (int i = 0; i < 32; i += 8) {
        int n = n0 + ty + i, k = k0 + tx;
        WtC[n * 128 + k] = tc[tx][ty + i];
        WtB[n * 128 + k] = tb[tx][ty + i];
    }
}
// W2 [512][128] -> W2t [128][512]
__global__ void tr_w2(const float* __restrict__ W2, float* __restrict__ W2t) {
    __shared__ float s[32][33];
    int k0 = blockIdx.x * 32, n0 = blockIdx.y * 32;
    int tx = threadIdx.x, ty = threadIdx.y;
#pragma unroll
    for (int i = 0; i < 32; i += 8)
        s[ty + i][tx] = W2[(k0 + ty + i) * 128 + n0 + tx];
    __syncthreads();
#pragma unroll
    for (int i = 0; i < 32; i += 8)
        W2t[(n0 + ty + i) * 512 + k0 + tx] = s[tx][ty + i];
}

// ---------------- edge / elementwise kernels ----------------
__global__ void fillk(float* __restrict__ p, int n, float v) {
    int i = blockIdx.x * blockDim.x + threadIdx.x;
    if (i < n) p[i] = v;
}
__global__ void finalize_max(float* __restrict__ p, int n) {
    int i = blockIdx.x * blockDim.x + threadIdx.x;
    if (i < n) { float v = p[i]; if (v < -3.0e38f) p[i] = 0.f; }
}
__global__ void bias_add(float* __restrict__ out, const float* __restrict__ b, int n) {
    int i = blockIdx.x * blockDim.x + threadIdx.x;
    if (i < n) out[i] += b[i & 127];
}
__global__ void rowdot(const float* __restrict__ X, const float* __restrict__ v,
                       float* __restrict__ out, int M) {
    int w = (blockIdx.x * blockDim.x + threadIdx.x) >> 5;
    int lane = threadIdx.x & 31;
    if (w >= M) return;
    float4 x = *(const float4*)&X[(size_t)w * 128 + lane * 4];
    float4 vv = *(const float4*)&v[lane * 4];
    float p = x.x * vv.x + x.y * vv.y + x.z * vv.z + x.w * vv.w;
#pragma unroll
    for (int o = 16; o; o >>= 1) p += __shfl_xor_sync(0xffffffffu, p, o);
    if (lane == 0) out[w] = p;
}
__global__ void trans_score_k(const float* __restrict__ q, const float* __restrict__ k,
                              const int* __restrict__ src, const int* __restrict__ dst,
                              float* __restrict__ score, float* __restrict__ nmax, int E) {
    int w = (blockIdx.x * blockDim.x + threadIdx.x) >> 5;
    int lane = threadIdx.x & 31;
    if (w >= E) return;
    int s = src[w], d = dst[w];
    float4 a = *(const float4*)&q[(size_t)d * 128 + lane * 4];
    float4 b = *(const float4*)&k[(size_t)s * 128 + lane * 4];
    float p = a.x * b.x + a.y * b.y + a.z * b.z + a.w * b.w;
#pragma unroll
    for (int o = 16; o; o >>= 1) p += __shfl_xor_sync(0xffffffffu, p, o);
    if (lane == 0) {
        p *= 0.08838834764831845f;
        score[w] = p;
        atomicMaxF(&nmax[d], p);
    }
}
__global__ void gat_score_k(const float* __restrict__ ssrc, const float* __restrict__ sdst,
                            const int* __restrict__ src, const int* __restrict__ dst,
                            float* __restrict__ score, float* __restrict__ nmax, int E) {
    int e = blockIdx.x * blockDim.x + threadIdx.x;
    if (e >= E) return;
    float s = ssrc[src[e]] + sdst[dst[e]];
    s = (s > 0.f) ? s : 0.2f * s;
    score[e] = s;
    atomicMaxF(&nmax[dst[e]], s);
}
__global__ void expnorm_k(float* __restrict__ score, const int* __restrict__ dst,
                          const float* __restrict__ nmax, float* __restrict__ nsum, int E) {
    int e = blockIdx.x * blockDim.x + threadIdx.x;
    if (e >= E) return;
    int d = dst[e];
    float v = __expf(score[e] - nmax[d]);
    score[e] = v;
    atomicAdd(&nsum[d], v);
}
__global__ void scatter_k(const float* __restrict__ score, const float* __restrict__ nsum,
                          const float* __restrict__ V,
                          const int* __restrict__ src, const int* __restrict__ dst,
                          float* __restrict__ out, int E) {
    int w = (blockIdx.x * blockDim.x + threadIdx.x) >> 5;
    int lane = threadIdx.x & 31;
    if (w >= E) return;
    int s = src[w], d = dst[w];
    float a = score[w] / (nsum[d] + 1e-16f);
    float4 v = *(const float4*)&V[(size_t)s * 128 + lane * 4];
    float* o = &out[(size_t)d * 128 + lane * 4];
    atomicAdd(o + 0, a * v.x);
    atomicAdd(o + 1, a * v.y);
    atomicAdd(o + 2, a * v.z);
    atomicAdd(o + 3, a * v.w);
}

// ---------------- host orchestration ----------------
static inline void run_gemm(const float* X, const float* W, const float* bias,
                            float* C, int M, int N, int ldw) {
    dim3 grid((M + 63) / 64, N / 128);
    gemm_tile<<<grid, 256>>>(X, W, bias, C, M, ldw, N);
}

struct Scratch {
    float *xL, *xP, *legoA, *pointA, *q, *k, *v, *hs, *A512, *B512;
    float *Wt1c, *Wt1b, *W2t;
    float *esc, *nmax, *nsum, *ssrc, *sdst, *waD;
};

static void trans_conv(const Scratch& S, const float* x, int Nn,
                       const int* src, const int* dst, int E,
                       const float* Wq, const float* bq, const float* Wk, const float* bk,
                       const float* Wv, const float* bv, const float* Ws, const float* bs,
                       float* out) {
    run_gemm(x, Wq, bq, S.q, Nn, 128, 128);
    run_gemm(x, Wk, bk, S.k, Nn, 128, 128);
    run_gemm(x, Wv, bv, S.v, Nn, 128, 128);
    run_gemm(x, Ws, bs, out, Nn, 128, 128);
    fillk<<<(Nn + 255) / 256, 256>>>(S.nmax, Nn, -INFINITY);
    fillk<<<(Nn + 255) / 256, 256>>>(S.nsum, Nn, 0.f);
    trans_score_k<<<(E + 7) / 8, 256>>>(S.q, S.k, src, dst, S.esc, S.nmax, E);
    expnorm_k<<<(E + 255) / 256, 256>>>(S.esc, dst, S.nmax, S.nsum, E);
    scatter_k<<<(E + 7) / 8, 256>>>(S.esc, S.nsum, S.v, src, dst, out, E);
}

static void gat_conv(const Scratch& S, const float* xs, int Ns, const float* xd, int Nd,
                     const int* src, const int* dst, int E,
                     const float* W, const float* As, const float* Ad, const float* b,
                     float* out) {
    run_gemm(xs, W, nullptr, S.hs, Ns, 128, 128);
    rowdot<<<(128 + 7) / 8, 256>>>(W, Ad, S.waD, 128);
    rowdot<<<(Ns + 7) / 8, 256>>>(S.hs, As, S.ssrc, Ns);
    rowdot<<<(Nd + 7) / 8, 256>>>(xd, S.waD, S.sdst, Nd);
    fillk<<<(Nd + 255) / 256, 256>>>(S.nmax, Nd, -INFINITY);
    fillk<<<(Nd + 255) / 256, 256>>>(S.nsum, Nd, 0.f);
    gat_score_k<<<(E + 255) / 256, 256>>>(S.ssrc, S.sdst, src, dst, S.esc, S.nmax, E);
    expnorm_k<<<(E + 255) / 256, 256>>>(S.esc, dst, S.nmax, S.nsum, E);
    scatter_k<<<(E + 7) / 8, 256>>>(S.esc, S.nsum, S.hs, src, dst, out, E);
    bias_add<<<(Nd * 128 + 255) / 256, 256>>>(out, b, Nd * 128);
}

static void edge_conv(const Scratch& S, const float* x, int Nn,
                      const int* src, const int* dst, int E,
                      const float* W1, const float* b1, const float* W2, const float* b2,
                      float* out) {
    tr_w1<<<dim3(4, 16), dim3(32, 8)>>>(W1, S.Wt1c, S.Wt1b);
    tr_w2<<<dim3(16, 4), dim3(32, 8)>>>(W2, S.W2t);
    gemm_tf32<<<dim3((Nn + 127) / 128, 4), 256>>>(x, S.Wt1c, b1, S.A512, Nn, 512);
    gemm_tf32<<<dim3((Nn + 127) / 128, 4), 256>>>(x, S.Wt1b, nullptr, S.B512, Nn, 512);
    fillk<<<(Nn * 128 + 255) / 256, 256>>>(out, Nn * 128, -INFINITY);
    edge_mlp2_tf32<<<(E + 127) / 128, 256>>>(S.A512, S.B512, src, dst, S.W2t, b2, out, E);
    finalize_max<<<(Nn * 128 + 255) / 256, 256>>>(out, Nn * 128);
}

#define GETSYM(field, symbol) do { void* _p; cudaGetSymbolAddress(&_p, symbol); S.field = (float*)_p; } while (0)

extern "C" void kernel_launch(void* const* d_in, const int* in_sizes, int n_in,
                              void* d_out, int out_size) {
    const float* in_xL  = (const float*)d_in[0];
    const float* in_xP  = (const float*)d_in[1];
    const float* tWq = (const float*)d_in[2];
    const float* tbq = (const float*)d_in[3];
    const float* tWk = (const float*)d_in[4];
    const float* tbk = (const float*)d_in[5];
    const float* tWv = (const float*)d_in[6];
    const float* tbv = (const float*)d_in[7];
    const float* tWs = (const float*)d_in[8];
    const float* tbs = (const float*)d_in[9];
    const float* eW1 = (const float*)d_in[10];
    const float* eb1 = (const float*)d_in[11];
    const float* eW2 = (const float*)d_in[12];
    const float* eb2 = (const float*)d_in[13];
    const float* gW  = (const float*)d_in[14];
    const float* gAs = (const float*)d_in[15];
    const float* gAd = (const float*)d_in[16];
    const float* gb  = (const float*)d_in[17];
    const int* ll_src = (const int*)d_in[18];
    const int* ll_dst = (const int*)d_in[19];
    const int* pp_src = (const int*)d_in[20];
    const int* pp_dst = (const int*)d_in[21];
    const int* lp_src = (const int*)d_in[22];
    const int* lp_dst = (const int*)d_in[23];
    const int* pl_src = (const int*)d_in[24];
    const int* pl_dst = (const int*)d_in[25];

    Scratch S;
    GETSYM(xL, g_xL);       GETSYM(xP, g_xP);
    GETSYM(legoA, g_legoA); GETSYM(pointA, g_pointA);
    GETSYM(q, g_q); GETSYM(k, g_k); GETSYM(v, g_v); GETSYM(hs, g_hs);
    GETSYM(A512, g_A512); GETSYM(B512, g_B512);
    GETSYM(Wt1c, g_Wt1c); GETSYM(Wt1b, g_Wt1b); GETSYM(W2t, g_W2t);
    GETSYM(esc, g_esc); GETSYM(nmax, g_nmax); GETSYM(nsum, g_nsum);
    GETSYM(ssrc, g_ssrc); GETSYM(sdst, g_sdst); GETSYM(waD, g_waD);

    cudaMemcpyAsync(S.xL, in_xL, (size_t)NL * DIM * sizeof(float), cudaMemcpyDeviceToDevice);
    cudaMemcpyAsync(S.xP, in_xP, (size_t)NP * DIM * sizeof(float), cudaMemcpyDeviceToDevice);

    for (int layer = 0; layer < 2; layer++) {
        int iA = 2 * layer, iB = 2 * layer + 1;
        int ilp = 2 * layer, ipl = 2 * layer + 1;

        trans_conv(S, S.xL, NL, ll_src, ll_dst, ELL,
                   tWq + iA * 16384, tbq + iA * 128, tWk + iA * 16384, tbk + iA * 128,
                   tWv + iA * 16384, tbv + iA * 128, tWs + iA * 16384, tbs + iA * 128,
                   S.legoA);
        gat_conv(S, S.xP, NP, S.xL, NL, pl_src, pl_dst, EPL,
                 gW + ipl * 16384, gAs + ipl * 128, gAd + ipl * 128, gb + ipl * 128,
                 S.legoA);
        edge_conv(S, S.xP, NP, pp_src, pp_dst, EPP,
                  eW1 + iA * 131072, eb1 + iA * 512, eW2 + iA * 65536, eb2 + iA * 128,
                  S.pointA);
        gat_conv(S, S.xL, NL, S.xP, NP, lp_src, lp_dst, ELP,
                 gW + ilp * 16384, gAs + ilp * 128, gAd + ilp * 128, gb + ilp * 128,
                 S.pointA);

        trans_conv(S, S.legoA, NL, ll_src, ll_dst, ELL,
                   tWq + iB * 16384, tbq + iB * 128, tWk + iB * 16384, tbk + iB * 128,
                   tWv + iB * 16384, tbv + iB * 128, tWs + iB * 16384, tbs + iB * 128,
                   S.xL);
        edge_conv(S, S.pointA, NP, pp_src, pp_dst, EPP,
                  eW1 + iB * 131072, eb1 + iB * 512, eW2 + iB * 65536, eb2 + iB * 128,
                  S.xP);
    }

    float* out = (float*)d_out;
    cudaMemcpyAsync(out, S.xL, (size_t)NL * DIM * sizeof(float), cudaMemcpyDeviceToDevice);
    cudaMemcpyAsync(out + (size_t)NL * DIM, S.xP, (size_t)NP * DIM * sizeof(float), cudaMemcpyDeviceToDevice);
}

// round 4
// speedup vs baseline: 2.3700x; 1.2462x over previous
#include <cuda_runtime.h>
#include <math.h>
#include <stdint.h>

#define DIM 128
#define NL 50000
#define NP 100000
#define ELL 500000
#define EPP 400000
#define ELP 500000
#define EPL 500000

// ---------------- scratch (device globals; allocation-free rule) ----------------
__device__ __align__(16) float g_xL[NL * DIM];
__device__ __align__(16) float g_xP[NP * DIM];
__device__ __align__(16) float g_legoA[NL * DIM];
__device__ __align__(16) float g_pointA[NP * DIM];
__device__ __align__(16) float g_q[NL * DIM];
__device__ __align__(16) float g_k[NL * DIM];
__device__ __align__(16) float g_v[NL * DIM];
__device__ __align__(16) float g_hs[NP * DIM];
__device__ __align__(16) float g_A512[NP * 512];
__device__ __align__(16) float g_B512[NP * 512];
__device__ __align__(16) float g_Wt1c[512 * 128];
__device__ __align__(16) float g_Wt1b[512 * 128];
__device__ __align__(16) float g_W2t[128 * 512];
__device__ __align__(16) float g_esc[500000];
__device__ __align__(16) float g_nmax[NP];
__device__ __align__(16) float g_nsum[NP];
__device__ __align__(16) float g_ssrc[NP];
__device__ __align__(16) float g_sdst[NP];
__device__ __align__(16) float g_waD[DIM];

// ---------------- small device helpers ----------------
__device__ __forceinline__ unsigned long long pack_dup(float x) {
    unsigned long long r;
    asm("mov.b64 %0, {%1, %1};" : "=l"(r) : "f"(x));
    return r;
}
__device__ __forceinline__ void ffma2(unsigned long long& d, unsigned long long a, unsigned long long b) {
    asm("fma.rn.f32x2 %0, %1, %2, %0;" : "+l"(d) : "l"(a), "l"(b));
}
__device__ __forceinline__ float2 unpk(unsigned long long u) {
    float2 f;
    asm("mov.b64 {%0, %1}, %2;" : "=f"(f.x), "=f"(f.y) : "l"(u));
    return f;
}
__device__ __forceinline__ void atomicMaxF(float* a, float v) {
    if (v >= 0.f) atomicMax((int*)a, __float_as_int(v));
    else          atomicMin((unsigned int*)a, __float_as_uint(v));
}
__device__ __forceinline__ uint32_t to_tf32(float x) {
    uint32_t r;
    asm("cvt.rna.tf32.f32 %0, %1;" : "=r"(r) : "f"(x));
    return r;
}
__device__ __forceinline__ void ldsm4(uint32_t& r0, uint32_t& r1, uint32_t& r2, uint32_t& r3, uint32_t addr) {
    asm volatile("ldmatrix.sync.aligned.m8n8.x4.shared.b16 {%0,%1,%2,%3}, [%4];"
                 : "=r"(r0), "=r"(r1), "=r"(r2), "=r"(r3) : "r"(addr));
}
__device__ __forceinline__ void mma_tf32(float* c, uint32_t a0, uint32_t a1, uint32_t a2, uint32_t a3,
                                         uint32_t b0, uint32_t b1) {
    asm volatile("mma.sync.aligned.m16n8k8.row.col.f32.tf32.tf32.f32 "
                 "{%0,%1,%2,%3},{%4,%5,%6,%7},{%8,%9},{%0,%1,%2,%3};"
                 : "+f"(c[0]), "+f"(c[1]), "+f"(c[2]), "+f"(c[3])
                 : "r"(a0), "r"(a1), "r"(a2), "r"(a3), "r"(b0), "r"(b1));
}
__device__ __forceinline__ void cp_async16(uint32_t saddr, const void* gaddr) {
    asm volatile("cp.async.cg.shared.global [%0], [%1], 16;" :: "r"(saddr), "l"(gaddr));
}
__device__ __forceinline__ void cp_commit() { asm volatile("cp.async.commit_group;"); }
__device__ __forceinline__ void cp_wait1() { asm volatile("cp.async.wait_group 1;" ::: "memory"); }
__device__ __forceinline__ void cp_wait0() { asm volatile("cp.async.wait_group 0;" ::: "memory"); }

// XOR-swizzled smem addressing: row stride 32 floats (128B), 16B groups g^(r&7).
// Conflict-free for both cp.async stores and ldmatrix reads; 16B aligned.
__device__ __forceinline__ uint32_t sw_addr(uint32_t base, int r, int g) {
    return base + (uint32_t)((r * 32 + (((g) ^ (r & 7)) << 2)) * 4);
}

// ---------------- fp32 FFMA GEMM (exact lego/gat path; numerics untouched) ----------------
__global__ __launch_bounds__(256) void gemm_tile(
    const float* __restrict__ X, const float* __restrict__ W,
    const float* __restrict__ bias, float* __restrict__ C,
    int M, int ldw, int ldc) {
    __shared__ __align__(16) float sX[64][36];
    __shared__ __align__(16) float sW[32][128];
    int t = threadIdx.x;
    int rowBase = blockIdx.x * 64;
    int colBase = blockIdx.y * 128;
    int rg = t >> 4, cg = t & 15;
    int r0 = rg * 4, c0 = cg * 8;
    unsigned long long acc[4][4];
#pragma unroll
    for (int r = 0; r < 4; r++)
#pragma unroll
        for (int p = 0; p < 4; p++) acc[r][p] = 0ull;
    int rA = t >> 3, kA = (t & 7) * 4;
    for (int kb = 0; kb < 128; kb += 32) {
#pragma unroll
        for (int i = 0; i < 2; i++) {
            int r = rA + i * 32;
            int row = rowBase + r; if (row >= M) row = M - 1;
            *(float4*)&sX[r][kA] = *(const float4*)&X[(size_t)row * 128 + kb + kA];
        }
#pragma unroll
        for (int i = 0; i < 4; i++) {
            int lin = t + i * 256;
            int k = lin >> 5, c4 = (lin & 31) * 4;
            *(float4*)&sW[k][c4] = *(const float4*)&W[(size_t)(kb + k) * ldw + colBase + c4];
        }
        __syncthreads();
#pragma unroll
        for (int k = 0; k < 32; k++) {
            ulonglong2 wa = *(const ulonglong2*)&sW[k][c0];
            ulonglong2 wb = *(const ulonglong2*)&sW[k][c0 + 4];
#pragma unroll
            for (int r = 0; r < 4; r++) {
                unsigned long long hp = pack_dup(sX[r0 + r][k]);
                ffma2(acc[r][0], hp, wa.x);
                ffma2(acc[r][1], hp, wa.y);
                ffma2(acc[r][2], hp, wb.x);
                ffma2(acc[r][3], hp, wb.y);
            }
        }
        __syncthreads();
    }
#pragma unroll
    for (int r = 0; r < 4; r++) {
        int row = rowBase + r0 + r;
        if (row >= M) continue;
        float o[8];
#pragma unroll
        for (int p = 0; p < 4; p++) { float2 f = unpk(acc[r][p]); o[2*p] = f.x; o[2*p+1] = f.y; }
        if (bias) {
#pragma unroll
            for (int j = 0; j < 8; j++) o[j] += bias[colBase + c0 + j];
        }
        *(float4*)&C[(size_t)row * ldc + colBase + c0]     = make_float4(o[0], o[1], o[2], o[3]);
        *(float4*)&C[(size_t)row * ldc + colBase + c0 + 4] = make_float4(o[4], o[5], o[6], o[7]);
    }
}

// ---------------- pipelined tf32 node GEMM: C[M,N] = X[M,128] @ Wt[N][128]^T ----------------
// BM=128, BN=128, BK=32 (4 stages over K=128), 2-stage cp.async ring.
// Stage layout (bytes): X tile at +0 (16KB), W tile at +16384. Stage stride 32768.
__global__ __launch_bounds__(256) void gemm_tf32_pipe(
    const float* __restrict__ X, const float* __restrict__ Wt,
    const float* __restrict__ bias, float* __restrict__ C, int M, int N) {
    extern __shared__ __align__(16) float smemBuf[];
    uint32_t sBase = (uint32_t)__cvta_generic_to_shared(smemBuf);
    int t = threadIdx.x;
    int rowBase = blockIdx.x * 128;
    int colBase = blockIdx.y * 128;
    int warp = t >> 5, lane = t & 31;
    int wm = warp >> 2, wn = warp & 3;
    int mBase = wm * 64, nBase = wn * 32;
    int lr = lane & 15, lh = lane >> 4;

    auto prefetch = [&](int it) {
        int k0 = it * 32;
        uint32_t stg = sBase + (uint32_t)((it & 1) * 32768);
#pragma unroll
        for (int i = 0; i < 4; i++) {
            int c = t + i * 256;
            int r = c >> 3, g = c & 7;
            int row = rowBase + r; if (row >= M) row = M - 1;
            cp_async16(sw_addr(stg, r, g), X + (size_t)row * 128 + k0 + g * 4);
            cp_async16(sw_addr(stg + 16384, r, g), Wt + (size_t)(colBase + r) * 128 + k0 + g * 4);
        }
        cp_commit();
    };

    float acc[4][4][4];
#pragma unroll
    for (int a = 0; a < 4; a++)
#pragma unroll
        for (int b = 0; b < 4; b++)
#pragma unroll
            for (int c = 0; c < 4; c++) acc[a][b][c] = 0.f;

    prefetch(0);
    for (int it = 0; it < 4; it++) {
        if (it + 1 < 4) { prefetch(it + 1); cp_wait1(); } else { cp_wait0(); }
        __syncthreads();
        uint32_t stg = sBase + (uint32_t)((it & 1) * 32768);
#pragma unroll
        for (int ks = 0; ks < 4; ks++) {
            int g = ks * 2 + lh;
            uint32_t a[4][4], b[2][4];
#pragma unroll
            for (int mt = 0; mt < 4; mt++) {
                int row = mBase + mt * 16 + lr;
                uint32_t r0, r1, r2, r3;
                ldsm4(r0, r1, r2, r3, sw_addr(stg, row, g));
                a[mt][0] = to_tf32(__uint_as_float(r0));
                a[mt][1] = to_tf32(__uint_as_float(r1));
                a[mt][2] = to_tf32(__uint_as_float(r2));
                a[mt][3] = to_tf32(__uint_as_float(r3));
            }
#pragma unroll
            for (int p = 0; p < 2; p++) {
                int row = nBase + p * 16 + lr;
                uint32_t r0, r1, r2, r3;
                ldsm4(r0, r1, r2, r3, sw_addr(stg + 16384, row, g));
                b[p][0] = to_tf32(__uint_as_float(r0));
                b[p][1] = to_tf32(__uint_as_float(r1));
                b[p][2] = to_tf32(__uint_as_float(r2));
                b[p][3] = to_tf32(__uint_as_float(r3));
            }
#pragma unroll
            for (int mt = 0; mt < 4; mt++)
#pragma unroll
                for (int nt = 0; nt < 4; nt++) {
                    int p = nt >> 1, wsel = nt & 1;
                    mma_tf32(acc[mt][nt], a[mt][0], a[mt][1], a[mt][2], a[mt][3],
                             b[p][wsel], b[p][2 + wsel]);
                }
        }
        __syncthreads();
    }
    int g = lane >> 2, tq = lane & 3;
#pragma unroll
    for (int mt = 0; mt < 4; mt++)
#pragma unroll
        for (int nt = 0; nt < 4; nt++) {
            int col = colBase + nBase + nt * 8 + tq * 2;
            float b0 = bias ? bias[col] : 0.f;
            float b1 = bias ? bias[col + 1] : 0.f;
            int row = rowBase + mBase + mt * 16 + g;
            if (row < M)
                *(float2*)&C[(size_t)row * N + col] = make_float2(acc[mt][nt][0] + b0, acc[mt][nt][1] + b1);
            row += 8;
            if (row < M)
                *(float2*)&C[(size_t)row * N + col] = make_float2(acc[mt][nt][2] + b0, acc[mt][nt][3] + b1);
        }
}

// ---------------- pipelined tf32 EdgeConv 2nd layer ----------------
// Per 128-edge tile: h = relu(A[dst]+B[src]) fused in registers from matching fragments.
// Stage layout: A at +0 (16KB), B at +16384, W at +32768. Stage stride 49152. 16 K-chunks.
__global__ __launch_bounds__(256) void edge_mlp2_tf32_pipe(
    const float* __restrict__ Ad, const float* __restrict__ Bs,
    const int* __restrict__ src, const int* __restrict__ dst,
    const float* __restrict__ W2t, const float* __restrict__ b2,
    float* __restrict__ out, int E) {
    extern __shared__ __align__(16) float smemBuf[];
    uint32_t sBase = (uint32_t)__cvta_generic_to_shared(smemBuf);
    __shared__ int sSrc[128], sDst[128];
    int t = threadIdx.x;
    int eBase = blockIdx.x * 128;
    if (t < 128) {
        int e = eBase + t; if (e >= E) e = E - 1;
        sSrc[t] = src[e]; sDst[t] = dst[e];
    }
    __syncthreads();
    int warp = t >> 5, lane = t & 31;
    int wm = warp >> 2, wn = warp & 3;
    int mBase = wm * 64, nBase = wn * 32;
    int lr = lane & 15, lh = lane >> 4;

    auto prefetch = [&](int it) {
        int k0 = it * 32;
        uint32_t stg = sBase + (uint32_t)((it & 1) * 49152);
#pragma unroll
        for (int i = 0; i < 4; i++) {
            int c = t + i * 256;
            int r = c >> 3, g = c & 7;
            uint32_t aAddr = sw_addr(stg, r, g);
            cp_async16(aAddr,         Ad  + (size_t)sDst[r] * 512 + k0 + g * 4);
            cp_async16(aAddr + 16384, Bs  + (size_t)sSrc[r] * 512 + k0 + g * 4);
            cp_async16(aAddr + 32768, W2t + (size_t)r * 512 + k0 + g * 4);
        }
        cp_commit();
    };

    float acc[4][4][4];
#pragma unroll
    for (int a = 0; a < 4; a++)
#pragma unroll
        for (int b = 0; b < 4; b++)
#pragma unroll
            for (int c = 0; c < 4; c++) acc[a][b][c] = 0.f;

    prefetch(0);
    for (int it = 0; it < 16; it++) {
        if (it + 1 < 16) { prefetch(it + 1); cp_wait1(); } else { cp_wait0(); }
        __syncthreads();
        uint32_t stg = sBase + (uint32_t)((it & 1) * 49152);
#pragma unroll
        for (int ks = 0; ks < 4; ks++) {
            int g = ks * 2 + lh;
            uint32_t a[4][4], b[2][4];
#pragma unroll
            for (int mt = 0; mt < 4; mt++) {
                int row = mBase + mt * 16 + lr;
                uint32_t addr = sw_addr(stg, row, g);
                uint32_t a0, a1, a2, a3, c0, c1, c2, c3;
                ldsm4(a0, a1, a2, a3, addr);
                ldsm4(c0, c1, c2, c3, addr + 16384);
                a[mt][0] = to_tf32(fmaxf(__uint_as_float(a0) + __uint_as_float(c0), 0.f));
                a[mt][1] = to_tf32(fmaxf(__uint_as_float(a1) + __uint_as_float(c1), 0.f));
                a[mt][2] = to_tf32(fmaxf(__uint_as_float(a2) + __uint_as_float(c2), 0.f));
                a[mt][3] = to_tf32(fmaxf(__uint_as_float(a3) + __uint_as_float(c3), 0.f));
            }
#pragma unroll
            for (int p = 0; p < 2; p++) {
                int row = nBase + p * 16 + lr;
                uint32_t r0, r1, r2, r3;
                ldsm4(r0, r1, r2, r3, sw_addr(stg + 32768, row, g));
                b[p][0] = to_tf32(__uint_as_float(r0));
                b[p][1] = to_tf32(__uint_as_float(r1));
                b[p][2] = to_tf32(__uint_as_float(r2));
                b[p][3] = to_tf32(__uint_as_float(r3));
            }
#pragma unroll
            for (int mt = 0; mt < 4; mt++)
#pragma unroll
                for (int nt = 0; nt < 4; nt++) {
                    int p = nt >> 1, wsel = nt & 1;
                    mma_tf32(acc[mt][nt], a[mt][0], a[mt][1], a[mt][2], a[mt][3],
                             b[p][wsel], b[p][2 + wsel]);
                }
        }
        __syncthreads();
    }
    int g = lane >> 2, tq = lane & 3;
#pragma unroll
    for (int mt = 0; mt < 4; mt++)
#pragma unroll
        for (int nt = 0; nt < 4; nt++) {
            int col = nBase + nt * 8 + tq * 2;
            float b0 = b2[col], b1 = b2[col + 1];
            int r = mBase + mt * 16 + g;
            if (eBase + r < E) {
                float* o = &out[(size_t)sDst[r] * 128 + col];
                atomicMaxF(o,     acc[mt][nt][0] + b0);
                atomicMaxF(o + 1, acc[mt][nt][1] + b1);
            }
            r += 8;
            if (eBase + r < E) {
                float* o = &out[(size_t)sDst[r] * 128 + col];
                atomicMaxF(o,     acc[mt][nt][2] + b0);
                atomicMaxF(o + 1, acc[mt][nt][3] + b1);
            }
        }
}

// ---------------- weight transposes for tf32 path ----------------
__global__ void tr_w1(const float* __restrict__ W1, float* __restrict__ WtC, float* __restrict__ WtB) {
    __shared__ float tc[32][33], tb[32][33];
    int k0 = blockIdx.x * 32, n0 = blockIdx.y * 32;
    int tx = threadIdx.x, ty = threadIdx.y;
#pragma unroll
    for (int i = 0; i < 32; i += 8) {
        int k = k0 + ty + i, n = n0 + tx;
        float top = W1[k * 512 + n], bot = W1[(k + 128) * 512 + n];
        tc[ty + i][tx] = top - bot;
        tb[ty + i][tx] = bot;
    }
    __syncthreads();
#pragma unroll
    for (int i = 0; i < 32; i += 8) {
        int n = n0 + ty + i, k = k0 + tx;
        WtC[n * 128 + k] = tc[tx][ty + i];
        WtB[n * 128 + k] = tb[tx][ty + i];
    }
}
__global__ void tr_w2(const float* __restrict__ W2, float* __restrict__ W2t) {
    __shared__ float s[32][33];
    int k0 = blockIdx.x * 32, n0 = blockIdx.y * 32;
    int tx = threadIdx.x, ty = threadIdx.y;
#pragma unroll
    for (int i = 0; i < 32; i += 8)
        s[ty + i][tx] = W2[(k0 + ty + i) * 128 + n0 + tx];
    __syncthreads();
#pragma unroll
    for (int i = 0; i < 32; i += 8)
        W2t[(n0 + ty + i) * 512 + k0 + tx] = s[tx][ty + i];
}

// ---------------- edge / elementwise kernels ----------------
__global__ void fillk(float* __restrict__ p, int n, float v) {
    int i = blockIdx.x * blockDim.x + threadIdx.x;
    if (i < n) p[i] = v;
}
__global__ void finalize_max(float* __restrict__ p, int n) {
    int i = blockIdx.x * blockDim.x + threadIdx.x;
    if (i < n) { float v = p[i]; if (v < -3.0e38f) p[i] = 0.f; }
}
__global__ void bias_add(float* __restrict__ out, const float* __restrict__ b, int n) {
    int i = blockIdx.x * blockDim.x + threadIdx.x;
    if (i < n) out[i] += b[i & 127];
}
__global__ void rowdot(const float* __restrict__ X, const float* __restrict__ v,
                       float* __restrict__ out, int M) {
    int w = (blockIdx.x * blockDim.x + threadIdx.x) >> 5;
    int lane = threadIdx.x & 31;
    if (w >= M) return;
    float4 x = *(const float4*)&X[(size_t)w * 128 + lane * 4];
    float4 vv = *(const float4*)&v[lane * 4];
    float p = x.x * vv.x + x.y * vv.y + x.z * vv.z + x.w * vv.w;
#pragma unroll
    for (int o = 16; o; o >>= 1) p += __shfl_xor_sync(0xffffffffu, p, o);
    if (lane == 0) out[w] = p;
}
__global__ void trans_score_k(const float* __restrict__ q, const float* __restrict__ k,
                              const int* __restrict__ src, const int* __restrict__ dst,
                              float* __restrict__ score, float* __restrict__ nmax, int E) {
    int w = (blockIdx.x * blockDim.x + threadIdx.x) >> 5;
    int lane = threadIdx.x & 31;
    if (w >= E) return;
    int s = src[w], d = dst[w];
    float4 a = *(const float4*)&q[(size_t)d * 128 + lane * 4];
    float4 b = *(const float4*)&k[(size_t)s * 128 + lane * 4];
    float p = a.x * b.x + a.y * b.y + a.z * b.z + a.w * b.w;
#pragma unroll
    for (int o = 16; o; o >>= 1) p += __shfl_xor_sync(0xffffffffu, p, o);
    if (lane == 0) {
        p *= 0.08838834764831845f;
        score[w] = p;
        atomicMaxF(&nmax[d], p);
    }
}
__global__ void gat_score_k(const float* __restrict__ ssrc, const float* __restrict__ sdst,
                            const int* __restrict__ src, const int* __restrict__ dst,
                            float* __restrict__ score, float* __restrict__ nmax, int E) {
    int e = blockIdx.x * blockDim.x + threadIdx.x;
    if (e >= E) return;
    float s = ssrc[src[e]] + sdst[dst[e]];
    s = (s > 0.f) ? s : 0.2f * s;
    score[e] = s;
    atomicMaxF(&nmax[dst[e]], s);
}
__global__ void expnorm_k(float* __restrict__ score, const int* __restrict__ dst,
                          const float* __restrict__ nmax, float* __restrict__ nsum, int E) {
    int e = blockIdx.x * blockDim.x + threadIdx.x;
    if (e >= E) return;
    int d = dst[e];
    float v = __expf(score[e] - nmax[d]);
    score[e] = v;
    atomicAdd(&nsum[d], v);
}
__global__ void scatter_k(const float* __restrict__ score, const float* __restrict__ nsum,
                          const float* __restrict__ V,
                          const int* __restrict__ src, const int* __restrict__ dst,
                          float* __restrict__ out, int E) {
    int w = (blockIdx.x * blockDim.x + threadIdx.x) >> 5;
    int lane = threadIdx.x & 31;
    if (w >= E) return;
    int s = src[w], d = dst[w];
    float a = score[w] / (nsum[d] + 1e-16f);
    float4 v = *(const float4*)&V[(size_t)s * 128 + lane * 4];
    float* o = &out[(size_t)d * 128 + lane * 4];
    atomicAdd(o + 0, a * v.x);
    atomicAdd(o + 1, a * v.y);
    atomicAdd(o + 2, a * v.z);
    atomicAdd(o + 3, a * v.w);
}

// ---------------- host orchestration ----------------
#define GEMM_TF32_SMEM 65536
#define EDGE_TF32_SMEM 98304

static inline void run_gemm(const float* X, const float* W, const float* bias,
                            float* C, int M, int N, int ldw) {
    dim3 grid((M + 63) / 64, N / 128);
    gemm_tile<<<grid, 256>>>(X, W, bias, C, M, ldw, N);
}

struct Scratch {
    float *xL, *xP, *legoA, *pointA, *q, *k, *v, *hs, *A512, *B512;
    float *Wt1c, *Wt1b, *W2t;
    float *esc, *nmax, *nsum, *ssrc, *sdst, *waD;
};

static void trans_conv(const Scratch& S, const float* x, int Nn,
                       const int* src, const int* dst, int E,
                       const float* Wq, const float* bq, const float* Wk, const float* bk,
                       const float* Wv, const float* bv, const float* Ws, const float* bs,
                       float* out) {
    run_gemm(x, Wq, bq, S.q, Nn, 128, 128);
    run_gemm(x, Wk, bk, S.k, Nn, 128, 128);
    run_gemm(x, Wv, bv, S.v, Nn, 128, 128);
    run_gemm(x, Ws, bs, out, Nn, 128, 128);
    fillk<<<(Nn + 255) / 256, 256>>>(S.nmax, Nn, -INFINITY);
    fillk<<<(Nn + 255) / 256, 256>>>(S.nsum, Nn, 0.f);
    trans_score_k<<<(E + 7) / 8, 256>>>(S.q, S.k, src, dst, S.esc, S.nmax, E);
    expnorm_k<<<(E + 255) / 256, 256>>>(S.esc, dst, S.nmax, S.nsum, E);
    scatter_k<<<(E + 7) / 8, 256>>>(S.esc, S.nsum, S.v, src, dst, out, E);
}

static void gat_conv(const Scratch& S, const float* xs, int Ns, const float* xd, int Nd,
                     const int* src, const int* dst, int E,
                     const float* W, const float* As, const float* Ad, const float* b,
                     float* out) {
    run_gemm(xs, W, nullptr, S.hs, Ns, 128, 128);
    rowdot<<<(128 + 7) / 8, 256>>>(W, Ad, S.waD, 128);
    rowdot<<<(Ns + 7) / 8, 256>>>(S.hs, As, S.ssrc, Ns);
    rowdot<<<(Nd + 7) / 8, 256>>>(xd, S.waD, S.sdst, Nd);
    fillk<<<(Nd + 255) / 256, 256>>>(S.nmax, Nd, -INFINITY);
    fillk<<<(Nd + 255) / 256, 256>>>(S.nsum, Nd, 0.f);
    gat_score_k<<<(E + 255) / 256, 256>>>(S.ssrc, S.sdst, src, dst, S.esc, S.nmax, E);
    expnorm_k<<<(E + 255) / 256, 256>>>(S.esc, dst, S.nmax, S.nsum, E);
    scatter_k<<<(E + 7) / 8, 256>>>(S.esc, S.nsum, S.hs, src, dst, out, E);
    bias_add<<<(Nd * 128 + 255) / 256, 256>>>(out, b, Nd * 128);
}

static void edge_conv(const Scratch& S, const float* x, int Nn,
                      const int* src, const int* dst, int E,
                      const float* W1, const float* b1, const float* W2, const float* b2,
                      float* out) {
    tr_w1<<<dim3(4, 16), dim3(32, 8)>>>(W1, S.Wt1c, S.Wt1b);
    tr_w2<<<dim3(16, 4), dim3(32, 8)>>>(W2, S.W2t);
    gemm_tf32_pipe<<<dim3((Nn + 127) / 128, 4), 256, GEMM_TF32_SMEM>>>(x, S.Wt1c, b1, S.A512, Nn, 512);
    gemm_tf32_pipe<<<dim3((Nn + 127) / 128, 4), 256, GEMM_TF32_SMEM>>>(x, S.Wt1b, nullptr, S.B512, Nn, 512);
    fillk<<<(Nn * 128 + 255) / 256, 256>>>(out, Nn * 128, -INFINITY);
    edge_mlp2_tf32_pipe<<<(E + 127) / 128, 256, EDGE_TF32_SMEM>>>(S.A512, S.B512, src, dst, S.W2t, b2, out, E);
    finalize_max<<<(Nn * 128 + 255) / 256, 256>>>(out, Nn * 128);
}

#define GETSYM(field, symbol) do { void* _p; cudaGetSymbolAddress(&_p, symbol); S.field = (float*)_p; } while (0)

extern "C" void kernel_launch(void* const* d_in, const int* in_sizes, int n_in,
                              void* d_out, int out_size) {
    const float* in_xL  = (const float*)d_in[0];
    const float* in_xP  = (const float*)d_in[1];
    const float* tWq = (const float*)d_in[2];
    const float* tbq = (const float*)d_in[3];
    const float* tWk = (const float*)d_in[4];
    const float* tbk = (const float*)d_in[5];
    const float* tWv = (const float*)d_in[6];
    const float* tbv = (const float*)d_in[7];
    const float* tWs = (const float*)d_in[8];
    const float* tbs = (const float*)d_in[9];
    const float* eW1 = (const float*)d_in[10];
    const float* eb1 = (const float*)d_in[11];
    const float* eW2 = (const float*)d_in[12];
    const float* eb2 = (const float*)d_in[13];
    const float* gW  = (const float*)d_in[14];
    const float* gAs = (const float*)d_in[15];
    const float* gAd = (const float*)d_in[16];
    const float* gb  = (const float*)d_in[17];
    const int* ll_src = (const int*)d_in[18];
    const int* ll_dst = (const int*)d_in[19];
    const int* pp_src = (const int*)d_in[20];
    const int* pp_dst = (const int*)d_in[21];
    const int* lp_src = (const int*)d_in[22];
    const int* lp_dst = (const int*)d_in[23];
    const int* pl_src = (const int*)d_in[24];
    const int* pl_dst = (const int*)d_in[25];

    cudaFuncSetAttribute(gemm_tf32_pipe, cudaFuncAttributeMaxDynamicSharedMemorySize, GEMM_TF32_SMEM);
    cudaFuncSetAttribute(edge_mlp2_tf32_pipe, cudaFuncAttributeMaxDynamicSharedMemorySize, EDGE_TF32_SMEM);

    Scratch S;
    GETSYM(xL, g_xL);       GETSYM(xP, g_xP);
    GETSYM(legoA, g_legoA); GETSYM(pointA, g_pointA);
    GETSYM(q, g_q); GETSYM(k, g_k); GETSYM(v, g_v); GETSYM(hs, g_hs);
    GETSYM(A512, g_A512); GETSYM(B512, g_B512);
    GETSYM(Wt1c, g_Wt1c); GETSYM(Wt1b, g_Wt1b); GETSYM(W2t, g_W2t);
    GETSYM(esc, g_esc); GETSYM(nmax, g_nmax); GETSYM(nsum, g_nsum);
    GETSYM(ssrc, g_ssrc); GETSYM(sdst, g_sdst); GETSYM(waD, g_waD);

    cudaMemcpyAsync(S.xL, in_xL, (size_t)NL * DIM * sizeof(float), cudaMemcpyDeviceToDevice);
    cudaMemcpyAsync(S.xP, in_xP, (size_t)NP * DIM * sizeof(float), cudaMemcpyDeviceToDevice);

    for (int layer = 0; layer < 2; layer++) {
        int iA = 2 * layer, iB = 2 * layer + 1;
        int ilp = 2 * layer, ipl = 2 * layer + 1;

        trans_conv(S, S.xL, NL, ll_src, ll_dst, ELL,
                   tWq + iA * 16384, tbq + iA * 128, tWk + iA * 16384, tbk + iA * 128,
                   tWv + iA * 16384, tbv + iA * 128, tWs + iA * 16384, tbs + iA * 128,
                   S.legoA);
        gat_conv(S, S.xP, NP, S.xL, NL, pl_src, pl_dst, EPL,
                 gW + ipl * 16384, gAs + ipl * 128, gAd + ipl * 128, gb + ipl * 128,
                 S.legoA);
        edge_conv(S, S.xP, NP, pp_src, pp_dst, EPP,
                  eW1 + iA * 131072, eb1 + iA * 512, eW2 + iA * 65536, eb2 + iA * 128,
                  S.pointA);
        gat_conv(S, S.xL, NL, S.xP, NP, lp_src, lp_dst, ELP,
                 gW + ilp * 16384, gAs + ilp * 128, gAd + ilp * 128, gb + ilp * 128,
                 S.pointA);

        trans_conv(S, S.legoA, NL, ll_src, ll_dst, ELL,
                   tWq + iB * 16384, tbq + iB * 128, tWk + iB * 16384, tbk + iB * 128,
                   tWv + iB * 16384, tbv + iB * 128, tWs + iB * 16384, tbs + iB * 128,
                   S.xL);
        edge_conv(S, S.pointA, NP, pp_src, pp_dst, EPP,
                  eW1 + iB * 131072, eb1 + iB * 512, eW2 + iB * 65536, eb2 + iB * 128,
                  S.xP);
    }

    float* out = (float*)d_out;
    cudaMemcpyAsync(out, S.xL, (size_t)NL * DIM * sizeof(float), cudaMemcpyDeviceToDevice);
    cudaMemcpyAsync(out + (size_t)NL * DIM, S.xP, (size_t)NP * DIM * sizeof(float), cudaMemcpyDeviceToDevice);
}

// round 5
// speedup vs baseline: 3.0739x; 1.2970x over previous
#include <cuda_runtime.h>
#include <math.h>
#include <stdint.h>

#define DIM 128
#define NL 50000
#define NP 100000
#define ELL 500000
#define EPP 400000
#define ELP 500000
#define EPL 500000

// ---------------- scratch (device globals; allocation-free rule) ----------------
__device__ __align__(16) float g_xL[NL * DIM];
__device__ __align__(16) float g_xP[NP * DIM];
__device__ __align__(16) float g_legoA[NL * DIM];
__device__ __align__(16) float g_pointA[NP * DIM];
__device__ __align__(16) float g_hs[NP * DIM];
__device__ __align__(16) float g_A512[NP * 512];   // also aliased as qkvs[NL*512] (disjoint lifetimes)
__device__ __align__(16) float g_B512[NP * 512];
__device__ __align__(16) float g_Wt1c[512 * 128];
__device__ __align__(16) float g_Wt1b[512 * 128];
__device__ __align__(16) float g_W2t[128 * 512];
__device__ __align__(16) float g_Wt4[512 * 128];
__device__ __align__(16) float g_b4[512];
__device__ __align__(16) float g_WtG[128 * 128];
__device__ __align__(16) float g_esc[500000];
__device__ __align__(16) float g_nmax[NP];
__device__ __align__(16) float g_nsum[NP];
__device__ __align__(16) float g_ssrc[NP];
__device__ __align__(16) float g_sdst[NP];
__device__ __align__(16) float g_waD[DIM];

// ---------------- small device helpers ----------------
__device__ __forceinline__ void atomicMaxF(float* a, float v) {
    if (v >= 0.f) atomicMax((int*)a, __float_as_int(v));
    else          atomicMin((unsigned int*)a, __float_as_uint(v));
}
__device__ __forceinline__ uint32_t to_tf32(float x) {
    uint32_t r;
    asm("cvt.rna.tf32.f32 %0, %1;" : "=r"(r) : "f"(x));
    return r;
}
__device__ __forceinline__ void ldsm4(uint32_t& r0, uint32_t& r1, uint32_t& r2, uint32_t& r3, uint32_t addr) {
    asm volatile("ldmatrix.sync.aligned.m8n8.x4.shared.b16 {%0,%1,%2,%3}, [%4];"
                 : "=r"(r0), "=r"(r1), "=r"(r2), "=r"(r3) : "r"(addr));
}
__device__ __forceinline__ void mma_tf32(float* c, const uint32_t* a, uint32_t b0, uint32_t b1) {
    asm volatile("mma.sync.aligned.m16n8k8.row.col.f32.tf32.tf32.f32 "
                 "{%0,%1,%2,%3},{%4,%5,%6,%7},{%8,%9},{%0,%1,%2,%3};"
                 : "+f"(c[0]), "+f"(c[1]), "+f"(c[2]), "+f"(c[3])
                 : "r"(a[0]), "r"(a[1]), "r"(a[2]), "r"(a[3]), "r"(b0), "r"(b1));
}
__device__ __forceinline__ void cp_async16(uint32_t saddr, const void* gaddr) {
    asm volatile("cp.async.cg.shared.global [%0], [%1], 16;" :: "r"(saddr), "l"(gaddr));
}
__device__ __forceinline__ void cp_commit() { asm volatile("cp.async.commit_group;"); }
__device__ __forceinline__ void cp_wait1() { asm volatile("cp.async.wait_group 1;" ::: "memory"); }
__device__ __forceinline__ void cp_wait0() { asm volatile("cp.async.wait_group 0;" ::: "memory"); }
__device__ __forceinline__ void red_add_v4(float* p, float4 v) {
    asm volatile("red.global.add.v4.f32 [%0], {%1,%2,%3,%4};"
                 :: "l"(p), "f"(v.x), "f"(v.y), "f"(v.z), "f"(v.w) : "memory");
}

// XOR-swizzled smem addressing: row stride 32 floats (128B), 16B groups g^(r&7).
__device__ __forceinline__ uint32_t sw_addr(uint32_t base, int r, int g) {
    return base + (uint32_t)((r * 32 + (((g) ^ (r & 7)) << 2)) * 4);
}

// ---------------- 3xTF32 pipelined node GEMM (fp32-accurate): C[M,N] = X[M,128] @ Wt[N][128]^T ----------------
// BM=128, BN=128, BK=32 (4 chunks), 2-stage cp.async ring, hi/lo mantissa split, 3 MMAs/pair.
__global__ __launch_bounds__(256) void gemm_3xtf32_pipe(
    const float* __restrict__ X, const float* __restrict__ Wt,
    const float* __restrict__ bias, float* __restrict__ C, int M, int N) {
    extern __shared__ __align__(16) float smemBuf[];
    uint32_t sBase = (uint32_t)__cvta_generic_to_shared(smemBuf);
    int t = threadIdx.x;
    int rowBase = blockIdx.x * 128;
    int colBase = blockIdx.y * 128;
    int warp = t >> 5, lane = t & 31;
    int wm = warp >> 2, wn = warp & 3;
    int mBase = wm * 64, nBase = wn * 32;
    int lr = lane & 15, lh = lane >> 4;

    auto prefetch = [&](int it) {
        int k0 = it * 32;
        uint32_t stg = sBase + (uint32_t)((it & 1) * 32768);
#pragma unroll
        for (int i = 0; i < 4; i++) {
            int c = t + i * 256;
            int r = c >> 3, g = c & 7;
            int row = rowBase + r; if (row >= M) row = M - 1;
            cp_async16(sw_addr(stg, r, g), X + (size_t)row * 128 + k0 + g * 4);
            cp_async16(sw_addr(stg + 16384, r, g), Wt + (size_t)(colBase + r) * 128 + k0 + g * 4);
        }
        cp_commit();
    };

    float acc[4][4][4];
#pragma unroll
    for (int a = 0; a < 4; a++)
#pragma unroll
        for (int b = 0; b < 4; b++)
#pragma unroll
            for (int c = 0; c < 4; c++) acc[a][b][c] = 0.f;

    prefetch(0);
    for (int it = 0; it < 4; it++) {
        if (it + 1 < 4) { prefetch(it + 1); cp_wait1(); } else { cp_wait0(); }
        __syncthreads();
        uint32_t stg = sBase + (uint32_t)((it & 1) * 32768);
#pragma unroll
        for (int ks = 0; ks < 4; ks++) {
            int g = ks * 2 + lh;
            uint32_t ah[4][4], al[4][4], bh[2][4], bl[2][4];
#pragma unroll
            for (int mt = 0; mt < 4; mt++) {
                int row = mBase + mt * 16 + lr;
                uint32_t r0, r1, r2, r3;
                ldsm4(r0, r1, r2, r3, sw_addr(stg, row, g));
                uint32_t raw[4] = {r0, r1, r2, r3};
#pragma unroll
                for (int j = 0; j < 4; j++) {
                    float f = __uint_as_float(raw[j]);
                    uint32_t hi = to_tf32(f);
                    ah[mt][j] = hi;
                    al[mt][j] = to_tf32(f - __uint_as_float(hi));
                }
            }
#pragma unroll
            for (int p = 0; p < 2; p++) {
                int row = nBase + p * 16 + lr;
                uint32_t r0, r1, r2, r3;
                ldsm4(r0, r1, r2, r3, sw_addr(stg + 16384, row, g));
                uint32_t raw[4] = {r0, r1, r2, r3};
#pragma unroll
                for (int j = 0; j < 4; j++) {
                    float f = __uint_as_float(raw[j]);
                    uint32_t hi = to_tf32(f);
                    bh[p][j] = hi;
                    bl[p][j] = to_tf32(f - __uint_as_float(hi));
                }
            }
#pragma unroll
            for (int mt = 0; mt < 4; mt++)
#pragma unroll
                for (int nt = 0; nt < 4; nt++) {
                    int p = nt >> 1, wsel = nt & 1;
                    mma_tf32(acc[mt][nt], al[mt], bh[p][wsel], bh[p][2 + wsel]);
                    mma_tf32(acc[mt][nt], ah[mt], bl[p][wsel], bl[p][2 + wsel]);
                    mma_tf32(acc[mt][nt], ah[mt], bh[p][wsel], bh[p][2 + wsel]);
                }
        }
        __syncthreads();
    }
    int g = lane >> 2, tq = lane & 3;
#pragma unroll
    for (int mt = 0; mt < 4; mt++)
#pragma unroll
        for (int nt = 0; nt < 4; nt++) {
            int col = colBase + nBase + nt * 8 + tq * 2;
            float b0 = bias ? bias[col] : 0.f;
            float b1 = bias ? bias[col + 1] : 0.f;
            int row = rowBase + mBase + mt * 16 + g;
            if (row < M)
                *(float2*)&C[(size_t)row * N + col] = make_float2(acc[mt][nt][0] + b0, acc[mt][nt][1] + b1);
            row += 8;
            if (row < M)
                *(float2*)&C[(size_t)row * N + col] = make_float2(acc[mt][nt][2] + b0, acc[mt][nt][3] + b1);
        }
}

// ---------------- pipelined tf32 node GEMM (single-pass; edge path, unchanged numerics) ----------------
__global__ __launch_bounds__(256) void gemm_tf32_pipe(
    const float* __restrict__ X, const float* __restrict__ Wt,
    const float* __restrict__ bias, float* __restrict__ C, int M, int N) {
    extern __shared__ __align__(16) float smemBuf[];
    uint32_t sBase = (uint32_t)__cvta_generic_to_shared(smemBuf);
    int t = threadIdx.x;
    int rowBase = blockIdx.x * 128;
    int colBase = blockIdx.y * 128;
    int warp = t >> 5, lane = t & 31;
    int wm = warp >> 2, wn = warp & 3;
    int mBase = wm * 64, nBase = wn * 32;
    int lr = lane & 15, lh = lane >> 4;

    auto prefetch = [&](int it) {
        int k0 = it * 32;
        uint32_t stg = sBase + (uint32_t)((it & 1) * 32768);
#pragma unroll
        for (int i = 0; i < 4; i++) {
            int c = t + i * 256;
            int r = c >> 3, g = c & 7;
            int row = rowBase + r; if (row >= M) row = M - 1;
            cp_async16(sw_addr(stg, r, g), X + (size_t)row * 128 + k0 + g * 4);
            cp_async16(sw_addr(stg + 16384, r, g), Wt + (size_t)(colBase + r) * 128 + k0 + g * 4);
        }
        cp_commit();
    };

    float acc[4][4][4];
#pragma unroll
    for (int a = 0; a < 4; a++)
#pragma unroll
        for (int b = 0; b < 4; b++)
#pragma unroll
            for (int c = 0; c < 4; c++) acc[a][b][c] = 0.f;

    prefetch(0);
    for (int it = 0; it < 4; it++) {
        if (it + 1 < 4) { prefetch(it + 1); cp_wait1(); } else { cp_wait0(); }
        __syncthreads();
        uint32_t stg = sBase + (uint32_t)((it & 1) * 32768);
#pragma unroll
        for (int ks = 0; ks < 4; ks++) {
            int g = ks * 2 + lh;
            uint32_t a[4][4], b[2][4];
#pragma unroll
            for (int mt = 0; mt < 4; mt++) {
                int row = mBase + mt * 16 + lr;
                uint32_t r0, r1, r2, r3;
                ldsm4(r0, r1, r2, r3, sw_addr(stg, row, g));
                a[mt][0] = to_tf32(__uint_as_float(r0));
                a[mt][1] = to_tf32(__uint_as_float(r1));
                a[mt][2] = to_tf32(__uint_as_float(r2));
                a[mt][3] = to_tf32(__uint_as_float(r3));
            }
#pragma unroll
            for (int p = 0; p < 2; p++) {
                int row = nBase + p * 16 + lr;
                uint32_t r0, r1, r2, r3;
                ldsm4(r0, r1, r2, r3, sw_addr(stg + 16384, row, g));
                b[p][0] = to_tf32(__uint_as_float(r0));
                b[p][1] = to_tf32(__uint_as_float(r1));
                b[p][2] = to_tf32(__uint_as_float(r2));
                b[p][3] = to_tf32(__uint_as_float(r3));
            }
#pragma unroll
            for (int mt = 0; mt < 4; mt++)
#pragma unroll
                for (int nt = 0; nt < 4; nt++) {
                    int p = nt >> 1, wsel = nt & 1;
                    mma_tf32(acc[mt][nt], a[mt], b[p][wsel], b[p][2 + wsel]);
                }
        }
        __syncthreads();
    }
    int g = lane >> 2, tq = lane & 3;
#pragma unroll
    for (int mt = 0; mt < 4; mt++)
#pragma unroll
        for (int nt = 0; nt < 4; nt++) {
            int col = colBase + nBase + nt * 8 + tq * 2;
            float b0 = bias ? bias[col] : 0.f;
            float b1 = bias ? bias[col + 1] : 0.f;
            int row = rowBase + mBase + mt * 16 + g;
            if (row < M)
                *(float2*)&C[(size_t)row * N + col] = make_float2(acc[mt][nt][0] + b0, acc[mt][nt][1] + b1);
            row += 8;
            if (row < M)
                *(float2*)&C[(size_t)row * N + col] = make_float2(acc[mt][nt][2] + b0, acc[mt][nt][3] + b1);
        }
}

// ---------------- pipelined tf32 EdgeConv 2nd layer (unchanged numerics from R4) ----------------
__global__ __launch_bounds__(256) void edge_mlp2_tf32_pipe(
    const float* __restrict__ Ad, const float* __restrict__ Bs,
    const int* __restrict__ src, const int* __restrict__ dst,
    const float* __restrict__ W2t, const float* __restrict__ b2,
    float* __restrict__ out, int E) {
    extern __shared__ __align__(16) float smemBuf[];
    uint32_t sBase = (uint32_t)__cvta_generic_to_shared(smemBuf);
    __shared__ int sSrc[128], sDst[128];
    int t = threadIdx.x;
    int eBase = blockIdx.x * 128;
    if (t < 128) {
        int e = eBase + t; if (e >= E) e = E - 1;
        sSrc[t] = src[e]; sDst[t] = dst[e];
    }
    __syncthreads();
    int warp = t >> 5, lane = t & 31;
    int wm = warp >> 2, wn = warp & 3;
    int mBase = wm * 64, nBase = wn * 32;
    int lr = lane & 15, lh = lane >> 4;

    auto prefetch = [&](int it) {
        int k0 = it * 32;
        uint32_t stg = sBase + (uint32_t)((it & 1) * 49152);
#pragma unroll
        for (int i = 0; i < 4; i++) {
            int c = t + i * 256;
            int r = c >> 3, g = c & 7;
            uint32_t aAddr = sw_addr(stg, r, g);
            cp_async16(aAddr,         Ad  + (size_t)sDst[r] * 512 + k0 + g * 4);
            cp_async16(aAddr + 16384, Bs  + (size_t)sSrc[r] * 512 + k0 + g * 4);
            cp_async16(aAddr + 32768, W2t + (size_t)r * 512 + k0 + g * 4);
        }
        cp_commit();
    };

    float acc[4][4][4];
#pragma unroll
    for (int a = 0; a < 4; a++)
#pragma unroll
        for (int b = 0; b < 4; b++)
#pragma unroll
            for (int c = 0; c < 4; c++) acc[a][b][c] = 0.f;

    prefetch(0);
    for (int it = 0; it < 16; it++) {
        if (it + 1 < 16) { prefetch(it + 1); cp_wait1(); } else { cp_wait0(); }
        __syncthreads();
        uint32_t stg = sBase + (uint32_t)((it & 1) * 49152);
#pragma unroll
        for (int ks = 0; ks < 4; ks++) {
            int g = ks * 2 + lh;
            uint32_t a[4][4], b[2][4];
#pragma unroll
            for (int mt = 0; mt < 4; mt++) {
                int row = mBase + mt * 16 + lr;
                uint32_t addr = sw_addr(stg, row, g);
                uint32_t a0, a1, a2, a3, c0, c1, c2, c3;
                ldsm4(a0, a1, a2, a3, addr);
                ldsm4(c0, c1, c2, c3, addr + 16384);
                a[mt][0] = to_tf32(fmaxf(__uint_as_float(a0) + __uint_as_float(c0), 0.f));
                a[mt][1] = to_tf32(fmaxf(__uint_as_float(a1) + __uint_as_float(c1), 0.f));
                a[mt][2] = to_tf32(fmaxf(__uint_as_float(a2) + __uint_as_float(c2), 0.f));
                a[mt][3] = to_tf32(fmaxf(__uint_as_float(a3) + __uint_as_float(c3), 0.f));
            }
#pragma unroll
            for (int p = 0; p < 2; p++) {
                int row = nBase + p * 16 + lr;
                uint32_t r0, r1, r2, r3;
                ldsm4(r0, r1, r2, r3, sw_addr(stg + 32768, row, g));
                b[p][0] = to_tf32(__uint_as_float(r0));
                b[p][1] = to_tf32(__uint_as_float(r1));
                b[p][2] = to_tf32(__uint_as_float(r2));
                b[p][3] = to_tf32(__uint_as_float(r3));
            }
#pragma unroll
            for (int mt = 0; mt < 4; mt++)
#pragma unroll
                for (int nt = 0; nt < 4; nt++) {
                    int p = nt >> 1, wsel = nt & 1;
                    mma_tf32(acc[mt][nt], a[mt], b[p][wsel], b[p][2 + wsel]);
                }
        }
        __syncthreads();
    }
    int g = lane >> 2, tq = lane & 3;
#pragma unroll
    for (int mt = 0; mt < 4; mt++)
#pragma unroll
        for (int nt = 0; nt < 4; nt++) {
            int col = nBase + nt * 8 + tq * 2;
            float b0 = b2[col], b1 = b2[col + 1];
            int r = mBase + mt * 16 + g;
            if (eBase + r < E) {
                float* o = &out[(size_t)sDst[r] * 128 + col];
                atomicMaxF(o,     acc[mt][nt][0] + b0);
                atomicMaxF(o + 1, acc[mt][nt][1] + b1);
            }
            r += 8;
            if (eBase + r < E) {
                float* o = &out[(size_t)sDst[r] * 128 + col];
                atomicMaxF(o,     acc[mt][nt][2] + b0);
                atomicMaxF(o + 1, acc[mt][nt][3] + b1);
            }
        }
}

// ---------------- weight packing / transposes ----------------
__global__ void tr_w1(const float* __restrict__ W1, float* __restrict__ WtC, float* __restrict__ WtB) {
    __shared__ float tc[32][33], tb[32][33];
    int k0 = blockIdx.x * 32, n0 = blockIdx.y * 32;
    int tx = threadIdx.x, ty = threadIdx.y;
#pragma unroll
    for (int i = 0; i < 32; i += 8) {
        int k = k0 + ty + i, n = n0 + tx;
        float top = W1[k * 512 + n], bot = W1[(k + 128) * 512 + n];
        tc[ty + i][tx] = top - bot;
        tb[ty + i][tx] = bot;
    }
    __syncthreads();
#pragma unroll
    for (int i = 0; i < 32; i += 8) {
        int n = n0 + ty + i, k = k0 + tx;
        WtC[n * 128 + k] = tc[tx][ty + i];
        WtB[n * 128 + k] = tb[tx][ty + i];
    }
}
__global__ void tr_w2(const float* __restrict__ W2, float* __restrict__ W2t) {
    __shared__ float s[32][33];
    int k0 = blockIdx.x * 32, n0 = blockIdx.y * 32;
    int tx = threadIdx.x, ty = threadIdx.y;
#pragma unroll
    for (int i = 0; i < 32; i += 8)
        s[ty + i][tx] = W2[(k0 + ty + i) * 128 + n0 + tx];
    __syncthreads();
#pragma unroll
    for (int i = 0; i < 32; i += 8)
        W2t[(n0 + ty + i) * 512 + k0 + tx] = s[tx][ty + i];
}
// Pack 4x [128][128] row-major weights into Wt4[512][128] transposed (Wt4[sel*128+n][k] = Wsel[k][n]).
__global__ void tr_pack4(const float* __restrict__ W0, const float* __restrict__ W1,
                         const float* __restrict__ W2, const float* __restrict__ W3,
                         float* __restrict__ Wt4) {
    __shared__ float s[32][33];
    int sel = blockIdx.z;
    const float* W = (sel == 0) ? W0 : (sel == 1) ? W1 : (sel == 2) ? W2 : W3;
    int k0 = blockIdx.x * 32, n0 = blockIdx.y * 32;
    int tx = threadIdx.x, ty = threadIdx.y;
#pragma unroll
    for (int i = 0; i < 32; i += 8)
        s[ty + i][tx] = W[(k0 + ty + i) * 128 + n0 + tx];
    __syncthreads();
#pragma unroll
    for (int i = 0; i < 32; i += 8)
        Wt4[(size_t)(sel * 128 + n0 + ty + i) * 128 + k0 + tx] = s[tx][ty + i];
}
__global__ void tr_sq(const float* __restrict__ W, float* __restrict__ Wt) {
    __shared__ float s[32][33];
    int k0 = blockIdx.x * 32, n0 = blockIdx.y * 32;
    int tx = threadIdx.x, ty = threadIdx.y;
#pragma unroll
    for (int i = 0; i < 32; i += 8)
        s[ty + i][tx] = W[(k0 + ty + i) * 128 + n0 + tx];
    __syncthreads();
#pragma unroll
    for (int i = 0; i < 32; i += 8)
        Wt[(n0 + ty + i) * 128 + k0 + tx] = s[tx][ty + i];
}
__global__ void pack4bias(const float* __restrict__ b0, const float* __restrict__ b1,
                          const float* __restrict__ b2, const float* __restrict__ b3,
                          float* __restrict__ b4) {
    int i = blockIdx.x * blockDim.x + threadIdx.x;
    if (i >= 512) return;
    int sel = i >> 7, j = i & 127;
    b4[i] = (sel == 0) ? b0[j] : (sel == 1) ? b1[j] : (sel == 2) ? b2[j] : b3[j];
}

// ---------------- edge / elementwise kernels ----------------
__global__ void fillk(float* __restrict__ p, int n, float v) {
    int i = blockIdx.x * blockDim.x + threadIdx.x;
    if (i < n) p[i] = v;
}
__global__ void finalize_max(float* __restrict__ p, int n) {
    int i = blockIdx.x * blockDim.x + threadIdx.x;
    if (i < n) { float v = p[i]; if (v < -3.0e38f) p[i] = 0.f; }
}
__global__ void bias_add(float* __restrict__ out, const float* __restrict__ b, int n) {
    int i = blockIdx.x * blockDim.x + threadIdx.x;
    if (i < n) out[i] += b[i & 127];
}
__global__ void copy_slice(const float* __restrict__ qkvs, float* __restrict__ out, int M) {
    int i = blockIdx.x * blockDim.x + threadIdx.x;
    if (i >= M * 32) return;
    int row = i >> 5, c = i & 31;
    *(float4*)&out[(size_t)row * 128 + c * 4] = *(const float4*)&qkvs[(size_t)row * 512 + 384 + c * 4];
}
__global__ void rowdot(const float* __restrict__ X, const float* __restrict__ v,
                       float* __restrict__ out, int M) {
    int w = (blockIdx.x * blockDim.x + threadIdx.x) >> 5;
    int lane = threadIdx.x & 31;
    if (w >= M) return;
    float4 x = *(const float4*)&X[(size_t)w * 128 + lane * 4];
    float4 vv = *(const float4*)&v[lane * 4];
    float p = x.x * vv.x + x.y * vv.y + x.z * vv.z + x.w * vv.w;
#pragma unroll
    for (int o = 16; o; o >>= 1) p += __shfl_xor_sync(0xffffffffu, p, o);
    if (lane == 0) out[w] = p;
}
// Transformer score over strided q/k tables (ld floats per row).
__global__ void trans_score_k(const float* __restrict__ q, const float* __restrict__ k, int ld,
                              const int* __restrict__ src, const int* __restrict__ dst,
                              float* __restrict__ score, float* __restrict__ nmax, int E) {
    int w = (blockIdx.x * blockDim.x + threadIdx.x) >> 5;
    int lane = threadIdx.x & 31;
    if (w >= E) return;
    int s = src[w], d = dst[w];
    float4 a = *(const float4*)&q[(size_t)d * ld + lane * 4];
    float4 b = *(const float4*)&k[(size_t)s * ld + lane * 4];
    float p = a.x * b.x + a.y * b.y + a.z * b.z + a.w * b.w;
#pragma unroll
    for (int o = 16; o; o >>= 1) p += __shfl_xor_sync(0xffffffffu, p, o);
    if (lane == 0) {
        p *= 0.08838834764831845f;
        score[w] = p;
        atomicMaxF(&nmax[d], p);
    }
}
__global__ void gat_score_k(const float* __restrict__ ssrc, const float* __restrict__ sdst,
                            const int* __restrict__ src, const int* __restrict__ dst,
                            float* __restrict__ score, float* __restrict__ nmax, int E) {
    int e = blockIdx.x * blockDim.x + threadIdx.x;
    if (e >= E) return;
    float s = ssrc[src[e]] + sdst[dst[e]];
    s = (s > 0.f) ? s : 0.2f * s;
    score[e] = s;
    atomicMaxF(&nmax[dst[e]], s);
}
__global__ void expnorm_k(float* __restrict__ score, const int* __restrict__ dst,
                          const float* __restrict__ nmax, float* __restrict__ nsum, int E) {
    int e = blockIdx.x * blockDim.x + threadIdx.x;
    if (e >= E) return;
    int d = dst[e];
    float v = __expf(score[e] - nmax[d]);
    score[e] = v;
    atomicAdd(&nsum[d], v);
}
// out[dst] += (score/sum)*V[src] with vector reductions (red.add.v4.f32).
__global__ void scatter_v4(const float* __restrict__ score, const float* __restrict__ nsum,
                           const float* __restrict__ V, int ldv,
                           const int* __restrict__ src, const int* __restrict__ dst,
                           float* __restrict__ out, int ldo, int E) {
    int w = (blockIdx.x * blockDim.x + threadIdx.x) >> 5;
    int lane = threadIdx.x & 31;
    if (w >= E) return;
    int s = src[w], d = dst[w];
    float a = score[w] / (nsum[d] + 1e-16f);
    float4 v = *(const float4*)&V[(size_t)s * ldv + lane * 4];
    red_add_v4(&out[(size_t)d * ldo + lane * 4], make_float4(a * v.x, a * v.y, a * v.z, a * v.w));
}

// ---------------- host orchestration ----------------
#define GEMM_TF32_SMEM 65536
#define EDGE_TF32_SMEM 98304

struct Scratch {
    float *xL, *xP, *legoA, *pointA, *hs, *A512, *B512;
    float *Wt1c, *Wt1b, *W2t, *Wt4, *b4, *WtG;
    float *esc, *nmax, *nsum, *ssrc, *sdst, *waD;
};

static void trans_conv(const Scratch& S, const float* x, int Nn,
                       const int* src, const int* dst, int E,
                       const float* Wq, const float* bq, const float* Wk, const float* bk,
                       const float* Wv, const float* bv, const float* Ws, const float* bs,
                       float* out) {
    float* qkvs = S.A512;  // alias; lifetimes disjoint with edge_conv
    tr_pack4<<<dim3(4, 4, 4), dim3(32, 8)>>>(Wq, Wk, Wv, Ws, S.Wt4);
    pack4bias<<<2, 256>>>(bq, bk, bv, bs, S.b4);
    gemm_3xtf32_pipe<<<dim3((Nn + 127) / 128, 4), 256, GEMM_TF32_SMEM>>>(x, S.Wt4, S.b4, qkvs, Nn, 512);
    fillk<<<(Nn + 255) / 256, 256>>>(S.nmax, Nn, -INFINITY);
    fillk<<<(Nn + 255) / 256, 256>>>(S.nsum, Nn, 0.f);
    trans_score_k<<<(E + 7) / 8, 256>>>(qkvs, qkvs + 128, 512, src, dst, S.esc, S.nmax, E);
    expnorm_k<<<(E + 255) / 256, 256>>>(S.esc, dst, S.nmax, S.nsum, E);
    scatter_v4<<<(E + 7) / 8, 256>>>(S.esc, S.nsum, qkvs + 256, 512, src, dst, qkvs + 384, 512, E);
    copy_slice<<<(Nn * 32 + 255) / 256, 256>>>(qkvs, out, Nn);
}

static void gat_conv(const Scratch& S, const float* xs, int Ns, const float* xd, int Nd,
                     const int* src, const int* dst, int E,
                     const float* W, const float* As, const float* Ad, const float* b,
                     float* out) {
    tr_sq<<<dim3(4, 4), dim3(32, 8)>>>(W, S.WtG);
    gemm_3xtf32_pipe<<<dim3((Ns + 127) / 128, 1), 256, GEMM_TF32_SMEM>>>(xs, S.WtG, nullptr, S.hs, Ns, 128);
    rowdot<<<(128 + 7) / 8, 256>>>(W, Ad, S.waD, 128);
    rowdot<<<(Ns + 7) / 8, 256>>>(S.hs, As, S.ssrc, Ns);
    rowdot<<<(Nd + 7) / 8, 256>>>(xd, S.waD, S.sdst, Nd);
    fillk<<<(Nd + 255) / 256, 256>>>(S.nmax, Nd, -INFINITY);
    fillk<<<(Nd + 255) / 256, 256>>>(S.nsum, Nd, 0.f);
    gat_score_k<<<(E + 255) / 256, 256>>>(S.ssrc, S.sdst, src, dst, S.esc, S.nmax, E);
    expnorm_k<<<(E + 255) / 256, 256>>>(S.esc, dst, S.nmax, S.nsum, E);
    scatter_v4<<<(E + 7) / 8, 256>>>(S.esc, S.nsum, S.hs, 128, src, dst, out, 128, E);
    bias_add<<<(Nd * 128 + 255) / 256, 256>>>(out, b, Nd * 128);
}

static void edge_conv(const Scratch& S, const float* x, int Nn,
                      const int* src, const int* dst, int E,
                      const float* W1, const float* b1, const float* W2, const float* b2,
                      float* out) {
    tr_w1<<<dim3(4, 16), dim3(32, 8)>>>(W1, S.Wt1c, S.Wt1b);
    tr_w2<<<dim3(16, 4), dim3(32, 8)>>>(W2, S.W2t);
    gemm_tf32_pipe<<<dim3((Nn + 127) / 128, 4), 256, GEMM_TF32_SMEM>>>(x, S.Wt1c, b1, S.A512, Nn, 512);
    gemm_tf32_pipe<<<dim3((Nn + 127) / 128, 4), 256, GEMM_TF32_SMEM>>>(x, S.Wt1b, nullptr, S.B512, Nn, 512);
    fillk<<<(Nn * 128 + 255) / 256, 256>>>(out, Nn * 128, -INFINITY);
    edge_mlp2_tf32_pipe<<<(E + 127) / 128, 256, EDGE_TF32_SMEM>>>(S.A512, S.B512, src, dst, S.W2t, b2, out, E);
    finalize_max<<<(Nn * 128 + 255) / 256, 256>>>(out, Nn * 128);
}

#define GETSYM(field, symbol) do { void* _p; cudaGetSymbolAddress(&_p, symbol); S.field = (float*)_p; } while (0)

extern "C" void kernel_launch(void* const* d_in, const int* in_sizes, int n_in,
                              void* d_out, int out_size) {
    const float* in_xL  = (const float*)d_in[0];
    const float* in_xP  = (const float*)d_in[1];
    const float* tWq = (const float*)d_in[2];
    const float* tbq = (const float*)d_in[3];
    const float* tWk = (const float*)d_in[4];
    const float* tbk = (const float*)d_in[5];
    const float* tWv = (const float*)d_in[6];
    const float* tbv = (const float*)d_in[7];
    const float* tWs = (const float*)d_in[8];
    const float* tbs = (const float*)d_in[9];
    const float* eW1 = (const float*)d_in[10];
    const float* eb1 = (const float*)d_in[11];
    const float* eW2 = (const float*)d_in[12];
    const float* eb2 = (const float*)d_in[13];
    const float* gW  = (const float*)d_in[14];
    const float* gAs = (const float*)d_in[15];
    const float* gAd = (const float*)d_in[16];
    const float* gb  = (const float*)d_in[17];
    const int* ll_src = (const int*)d_in[18];
    const int* ll_dst = (const int*)d_in[19];
    const int* pp_src = (const int*)d_in[20];
    const int* pp_dst = (const int*)d_in[21];
    const int* lp_src = (const int*)d_in[22];
    const int* lp_dst = (const int*)d_in[23];
    const int* pl_src = (const int*)d_in[24];
    const int* pl_dst = (const int*)d_in[25];

    cudaFuncSetAttribute(gemm_tf32_pipe, cudaFuncAttributeMaxDynamicSharedMemorySize, GEMM_TF32_SMEM);
    cudaFuncSetAttribute(gemm_3xtf32_pipe, cudaFuncAttributeMaxDynamicSharedMemorySize, GEMM_TF32_SMEM);
    cudaFuncSetAttribute(edge_mlp2_tf32_pipe, cudaFuncAttributeMaxDynamicSharedMemorySize, EDGE_TF32_SMEM);

    Scratch S;
    GETSYM(xL, g_xL);       GETSYM(xP, g_xP);
    GETSYM(legoA, g_legoA); GETSYM(pointA, g_pointA);
    GETSYM(hs, g_hs);
    GETSYM(A512, g_A512); GETSYM(B512, g_B512);
    GETSYM(Wt1c, g_Wt1c); GETSYM(Wt1b, g_Wt1b); GETSYM(W2t, g_W2t);
    GETSYM(Wt4, g_Wt4); GETSYM(b4, g_b4); GETSYM(WtG, g_WtG);
    GETSYM(esc, g_esc); GETSYM(nmax, g_nmax); GETSYM(nsum, g_nsum);
    GETSYM(ssrc, g_ssrc); GETSYM(sdst, g_sdst); GETSYM(waD, g_waD);

    cudaMemcpyAsync(S.xL, in_xL, (size_t)NL * DIM * sizeof(float), cudaMemcpyDeviceToDevice);
    cudaMemcpyAsync(S.xP, in_xP, (size_t)NP * DIM * sizeof(float), cudaMemcpyDeviceToDevice);

    for (int layer = 0; layer < 2; layer++) {
        int iA = 2 * layer, iB = 2 * layer + 1;
        int ilp = 2 * layer, ipl = 2 * layer + 1;

        trans_conv(S, S.xL, NL, ll_src, ll_dst, ELL,
                   tWq + iA * 16384, tbq + iA * 128, tWk + iA * 16384, tbk + iA * 128,
                   tWv + iA * 16384, tbv + iA * 128, tWs + iA * 16384, tbs + iA * 128,
                   S.legoA);
        gat_conv(S, S.xP, NP, S.xL, NL, pl_src, pl_dst, EPL,
                 gW + ipl * 16384, gAs + ipl * 128, gAd + ipl * 128, gb + ipl * 128,
                 S.legoA);
        edge_conv(S, S.xP, NP, pp_src, pp_dst, EPP,
                  eW1 + iA * 131072, eb1 + iA * 512, eW2 + iA * 65536, eb2 + iA * 128,
                  S.pointA);
        gat_conv(S, S.xL, NL, S.xP, NP, lp_src, lp_dst, ELP,
                 gW + ilp * 16384, gAs + ilp * 128, gAd + ilp * 128, gb + ilp * 128,
                 S.pointA);

        trans_conv(S, S.legoA, NL, ll_src, ll_dst, ELL,
                   tWq + iB * 16384, tbq + iB * 128, tWk + iB * 16384, tbk + iB * 128,
                   tWv + iB * 16384, tbv + iB * 128, tWs + iB * 16384, tbs + iB * 128,
                   S.xL);
        edge_conv(S, S.pointA, NP, pp_src, pp_dst, EPP,
                  eW1 + iB * 131072, eb1 + iB * 512, eW2 + iB * 65536, eb2 + iB * 128,
                  S.xP);
    }

    float* out = (float*)d_out;
    cudaMemcpyAsync(out, S.xL, (size_t)NL * DIM * sizeof(float), cudaMemcpyDeviceToDevice);
    cudaMemcpyAsync(out + (size_t)NL * DIM, S.xP, (size_t)NP * DIM * sizeof(float), cudaMemcpyDeviceToDevice);
}